// round 4
// baseline (speedup 1.0000x reference)
#include <cuda_runtime.h>
#include <cuda_bf16.h>

// Problem constants (fixed by reference): N=2, L=2048, EMBED=1024, HEADS=16, Dh=64
#define SEQ_LEN   2048
#define EMBED_DIM 1024
#define NTOK      4096          // N * L
#define HEAD_DIM  64

// ---------------- scratch (device globals: allocation-guard safe) ----------------
__device__ float g_Q [NTOK * EMBED_DIM];
__device__ float g_K [NTOK * EMBED_DIM];
__device__ float g_V [NTOK * EMBED_DIM];
__device__ float g_AO[NTOK * EMBED_DIM];

// Output selector: resolved in DEVICE code so kernel_launch needs no
// cudaGetSymbolAddress (keeps kernel_launch to pure kernel launches).
#define OUT_Q   0
#define OUT_K   1
#define OUT_V   2
#define OUT_EXT 4

__device__ __forceinline__ float* pick_out(int sel, float* ext) {
    switch (sel) {
        case OUT_Q:  return g_Q;
        case OUT_K:  return g_K;
        case OUT_V:  return g_V;
        default:     return ext;
    }
}

// =================================================================================
// GEMM:  C[M=4096, N=1024] = A[4096,1024] @ W[1024,1024]^T  (+ bias)
// C[i,j] = sum_k A[i,k] * W[j,k]   (torch Linear convention)
// Tile 128x64x16, 256 threads, thread computes 8x4.
// A == nullptr means "read the attention output scratch g_AO" (device-resolved).
// =================================================================================
#define BM 128
#define BN 64
#define BK 16

__global__ void __launch_bounds__(256) gemm_wt_kernel(
    const float* __restrict__ A_in,
    const float* __restrict__ W,
    const float* __restrict__ bias,   // may be nullptr
    int out_sel,
    float* ext_out)                   // used only when out_sel == OUT_EXT
{
    const float* __restrict__ A = A_in ? A_in : (const float*)g_AO;
    float* __restrict__ C = pick_out(out_sel, ext_out);

    __shared__ float As[BK][BM + 4];  // [k][m], row stride 132 floats (16B-mult)
    __shared__ float Bs[BK][BN + 4];  // [k][n], row stride 68 floats

    const int tid = threadIdx.x;
    const int tx  = tid & 15;         // 0..15 -> n cols tx*4..+3
    const int ty  = tid >> 4;         // 0..15 -> m rows ty*8..+7
    const int m0  = blockIdx.y * BM;
    const int n0  = blockIdx.x * BN;

    float acc[8][4];
    #pragma unroll
    for (int i = 0; i < 8; i++)
        #pragma unroll
        for (int j = 0; j < 4; j++) acc[i][j] = 0.f;

    for (int k0 = 0; k0 < EMBED_DIM; k0 += BK) {
        // ---- load A tile (128x16): 512 float4, 2 per thread, transposed store
        #pragma unroll
        for (int i = 0; i < 2; i++) {
            int f  = tid + i * 256;          // 0..511
            int r  = f >> 2;                 // row 0..127
            int kc = (f & 3) * 4;            // k sub-chunk
            float4 v = *(const float4*)(A + (size_t)(m0 + r) * EMBED_DIM + k0 + kc);
            As[kc + 0][r] = v.x; As[kc + 1][r] = v.y;
            As[kc + 2][r] = v.z; As[kc + 3][r] = v.w;
        }
        // ---- load W tile (64x16): 256 float4, 1 per thread, transposed store
        {
            int r  = tid >> 2;               // row 0..63 (n)
            int kc = (tid & 3) * 4;
            float4 v = *(const float4*)(W + (size_t)(n0 + r) * EMBED_DIM + k0 + kc);
            Bs[kc + 0][r] = v.x; Bs[kc + 1][r] = v.y;
            Bs[kc + 2][r] = v.z; Bs[kc + 3][r] = v.w;
        }
        __syncthreads();

        #pragma unroll
        for (int kk = 0; kk < BK; kk++) {
            float4 a0 = *(const float4*)&As[kk][ty * 8];
            float4 a1 = *(const float4*)&As[kk][ty * 8 + 4];
            float4 b  = *(const float4*)&Bs[kk][tx * 4];
            float av[8] = {a0.x, a0.y, a0.z, a0.w, a1.x, a1.y, a1.z, a1.w};
            float bv[4] = {b.x, b.y, b.z, b.w};
            #pragma unroll
            for (int i = 0; i < 8; i++)
                #pragma unroll
                for (int j = 0; j < 4; j++)
                    acc[i][j] += av[i] * bv[j];
        }
        __syncthreads();
    }

    float4 bb = make_float4(0.f, 0.f, 0.f, 0.f);
    if (bias) bb = *(const float4*)(bias + n0 + tx * 4);

    #pragma unroll
    for (int i = 0; i < 8; i++) {
        int row = m0 + ty * 8 + i;
        float4 o = make_float4(acc[i][0] + bb.x, acc[i][1] + bb.y,
                               acc[i][2] + bb.z, acc[i][3] + bb.w);
        *(float4*)(C + (size_t)row * EMBED_DIM + n0 + tx * 4) = o;
    }
}

// =================================================================================
// Flash attention: per CTA one (batch,head, 64-q-row tile); stream K/V in 32-row
// tiles. 256 threads: tx=tid&15 -> 2 k-cols / 4 d-cols, ty=tid>>4 -> 4 q-rows.
// Online softmax with per-row state replicated across the 16-lane tx group
// (butterfly shfl reductions). Static smem = 44.0 KB.
// Reads g_Q/g_K/g_V directly, writes g_AO directly (no pointer plumbing).
// =================================================================================
#define AQ 64     // q rows per CTA
#define AK 32     // k rows per tile

__global__ void __launch_bounds__(256) attn_kernel(
    const int* __restrict__ mask)     // [N, L] (logical shape (N,1,1,L))
{
    const float* __restrict__ Q  = g_Q;
    const float* __restrict__ K  = g_K;
    const float* __restrict__ V  = g_V;
    float*       __restrict__ AO = g_AO;

    __shared__ float Qt[HEAD_DIM][AQ + 4];  // [d][q], pre-scaled by 1/8
    __shared__ float Kt[HEAD_DIM][AK + 2];  // [d][k], stride 34 floats (8B-mult)
    __shared__ float Vs[AK][HEAD_DIM + 4];  // [k][d]
    __shared__ float Pt[AK][AQ + 4];        // [k][q]
    __shared__ float mk[AK];                // 0 or -1e20 additive mask

    const int tid = threadIdx.x;
    const int tx  = tid & 15;
    const int ty  = tid >> 4;
    const int q0  = blockIdx.x * AQ;
    const int b   = blockIdx.y >> 4;
    const int h   = blockIdx.y & 15;
    const size_t base = (size_t)b * SEQ_LEN * EMBED_DIM + (size_t)h * HEAD_DIM;

    // ---- load Q tile (64x64), transpose + scale by 1/sqrt(Dh)=0.125
    #pragma unroll
    for (int i = 0; i < 4; i++) {
        int f  = tid + i * 256;              // 0..1023
        int r  = f >> 4;                     // q row 0..63
        int dc = (f & 15) * 4;               // d col
        float4 v = *(const float4*)(Q + base + (size_t)(q0 + r) * EMBED_DIM + dc);
        Qt[dc + 0][r] = v.x * 0.125f;
        Qt[dc + 1][r] = v.y * 0.125f;
        Qt[dc + 2][r] = v.z * 0.125f;
        Qt[dc + 3][r] = v.w * 0.125f;
    }

    float m_i[4], l_i[4], o[4][4];
    #pragma unroll
    for (int qi = 0; qi < 4; qi++) {
        m_i[qi] = -1e30f; l_i[qi] = 0.f;
        #pragma unroll
        for (int di = 0; di < 4; di++) o[qi][di] = 0.f;
    }

    for (int kt = 0; kt < SEQ_LEN; kt += AK) {
        __syncthreads();   // prior-iteration Pt/Vs reads done before overwrite
        // ---- load K (transposed) & V (natural): 32x64 each, 2 float4/thread each
        #pragma unroll
        for (int i = 0; i < 2; i++) {
            int f  = tid + i * 256;          // 0..511
            int r  = f >> 4;                 // k row 0..31
            int dc = (f & 15) * 4;
            float4 kv = *(const float4*)(K + base + (size_t)(kt + r) * EMBED_DIM + dc);
            Kt[dc + 0][r] = kv.x; Kt[dc + 1][r] = kv.y;
            Kt[dc + 2][r] = kv.z; Kt[dc + 3][r] = kv.w;
            float4 vv = *(const float4*)(V + base + (size_t)(kt + r) * EMBED_DIM + dc);
            *(float4*)&Vs[r][dc] = vv;
        }
        if (tid < AK)
            mk[tid] = (mask[b * SEQ_LEN + kt + tid] == 0) ? -1e20f : 0.f;
        __syncthreads();

        // ---- S = (Q/8) K^T  : 4q x 2k fragment per thread
        float s[4][2];
        #pragma unroll
        for (int qi = 0; qi < 4; qi++) { s[qi][0] = 0.f; s[qi][1] = 0.f; }
        #pragma unroll 8
        for (int d = 0; d < HEAD_DIM; d++) {
            float4 qv = *(const float4*)&Qt[d][ty * 4];
            float2 kv = *(const float2*)&Kt[d][tx * 2];
            s[0][0] += qv.x * kv.x;  s[0][1] += qv.x * kv.y;
            s[1][0] += qv.y * kv.x;  s[1][1] += qv.y * kv.y;
            s[2][0] += qv.z * kv.x;  s[2][1] += qv.z * kv.y;
            s[3][0] += qv.w * kv.x;  s[3][1] += qv.w * kv.y;
        }
        {
            float a0 = mk[tx * 2], a1 = mk[tx * 2 + 1];
            #pragma unroll
            for (int qi = 0; qi < 4; qi++) { s[qi][0] += a0; s[qi][1] += a1; }
        }

        // ---- online softmax (row state replicated across the 16-lane tx group)
        float p[4][2];
        #pragma unroll
        for (int qi = 0; qi < 4; qi++) {
            float tm = fmaxf(s[qi][0], s[qi][1]);
            #pragma unroll
            for (int off = 1; off < 16; off <<= 1)
                tm = fmaxf(tm, __shfl_xor_sync(0xffffffffu, tm, off));
            float mn    = fmaxf(m_i[qi], tm);
            float alpha = __expf(m_i[qi] - mn);
            m_i[qi] = mn;
            p[qi][0] = __expf(s[qi][0] - mn);
            p[qi][1] = __expf(s[qi][1] - mn);
            float rs = p[qi][0] + p[qi][1];
            #pragma unroll
            for (int off = 1; off < 16; off <<= 1)
                rs += __shfl_xor_sync(0xffffffffu, rs, off);
            l_i[qi] = l_i[qi] * alpha + rs;
            #pragma unroll
            for (int di = 0; di < 4; di++) o[qi][di] *= alpha;
        }

        // ---- write P transposed: Pt[k][q]
        #pragma unroll
        for (int ki = 0; ki < 2; ki++) {
            float4 pv = make_float4(p[0][ki], p[1][ki], p[2][ki], p[3][ki]);
            *(float4*)&Pt[tx * 2 + ki][ty * 4] = pv;
        }
        __syncthreads();

        // ---- O += P V : 4q x 4d fragment per thread
        #pragma unroll 8
        for (int k = 0; k < AK; k++) {
            float4 pv = *(const float4*)&Pt[k][ty * 4];
            float4 vv = *(const float4*)&Vs[k][tx * 4];
            o[0][0] += pv.x * vv.x; o[0][1] += pv.x * vv.y; o[0][2] += pv.x * vv.z; o[0][3] += pv.x * vv.w;
            o[1][0] += pv.y * vv.x; o[1][1] += pv.y * vv.y; o[1][2] += pv.y * vv.z; o[1][3] += pv.y * vv.w;
            o[2][0] += pv.z * vv.x; o[2][1] += pv.z * vv.y; o[2][2] += pv.z * vv.z; o[2][3] += pv.z * vv.w;
            o[3][0] += pv.w * vv.x; o[3][1] += pv.w * vv.y; o[3][2] += pv.w * vv.z; o[3][3] += pv.w * vv.w;
        }
    }

    // ---- epilogue: normalize and write AO[token][h*64 + d]
    #pragma unroll
    for (int qi = 0; qi < 4; qi++) {
        float inv = 1.f / l_i[qi];
        float4 ov = make_float4(o[qi][0] * inv, o[qi][1] * inv,
                                o[qi][2] * inv, o[qi][3] * inv);
        *(float4*)(AO + base + (size_t)(q0 + ty * 4 + qi) * EMBED_DIM + tx * 4) = ov;
    }
}

// =================================================================================
// kernel_launch: PURE kernel launches — no runtime API calls of any kind.
// =================================================================================
extern "C" void kernel_launch(void* const* d_in, const int* in_sizes, int n_in,
                              void* d_out, int out_size)
{
    const float* values = (const float*)d_in[0];
    const float* keys   = (const float*)d_in[1];
    const float* query  = (const float*)d_in[2];
    const int*   mask   = (const int*)  d_in[3];
    const float* W_q    = (const float*)d_in[4];
    const float* W_k    = (const float*)d_in[5];
    const float* W_v    = (const float*)d_in[6];
    const float* W_o    = (const float*)d_in[7];
    const float* b_o    = (const float*)d_in[8];
    float* out = (float*)d_out;

    dim3 ggrid(EMBED_DIM / BN, NTOK / BM);          // (16, 32) = 512 CTAs
    gemm_wt_kernel<<<ggrid, 256>>>(query,  W_q, nullptr, OUT_Q, nullptr);
    gemm_wt_kernel<<<ggrid, 256>>>(keys,   W_k, nullptr, OUT_K, nullptr);
    gemm_wt_kernel<<<ggrid, 256>>>(values, W_v, nullptr, OUT_V, nullptr);

    dim3 agrid(SEQ_LEN / AQ, 2 * 16);               // (32, 32) = 1024 CTAs
    attn_kernel<<<agrid, 256>>>(mask);

    // A == nullptr -> kernel reads g_AO (device-resolved)
    gemm_wt_kernel<<<ggrid, 256>>>(nullptr, W_o, b_o, OUT_EXT, out);
}

// round 5
// speedup vs baseline: 1.0027x; 1.0027x over previous
#include <cuda_runtime.h>
#include <cuda_bf16.h>

// Problem constants (fixed by reference): N=2, L=2048, EMBED=1024, HEADS=16, Dh=64
#define SEQ_LEN   2048
#define EMBED_DIM 1024
#define NTOK      4096          // N * L
#define HEAD_DIM  64

// ---------------- scratch (device globals: allocation-guard safe) ----------------
__device__ float g_Q [NTOK * EMBED_DIM];
__device__ float g_K [NTOK * EMBED_DIM];
__device__ float g_V [NTOK * EMBED_DIM];
__device__ float g_AO[NTOK * EMBED_DIM];

// Output selector: resolved in DEVICE code so kernel_launch needs no
// cudaGetSymbolAddress (keeps kernel_launch to pure kernel launches).
#define OUT_Q   0
#define OUT_K   1
#define OUT_V   2
#define OUT_EXT 4

__device__ __forceinline__ float* pick_out(int sel, float* ext) {
    switch (sel) {
        case OUT_Q:  return g_Q;
        case OUT_K:  return g_K;
        case OUT_V:  return g_V;
        default:     return ext;
    }
}

// =================================================================================
// GEMM:  C[M=4096, N=1024] = A[4096,1024] @ W[1024,1024]^T  (+ bias)
// C[i,j] = sum_k A[i,k] * W[j,k]   (torch Linear convention)
// Tile 128x64x16, 256 threads, thread computes 8x4.
// A == nullptr means "read the attention output scratch g_AO" (device-resolved).
// =================================================================================
#define BM 128
#define BN 64
#define BK 16

__global__ void __launch_bounds__(256) gemm_wt_kernel(
    const float* __restrict__ A_in,
    const float* __restrict__ W,
    const float* __restrict__ bias,   // may be nullptr
    int out_sel,
    float* ext_out)                   // used only when out_sel == OUT_EXT
{
    const float* __restrict__ A = A_in ? A_in : (const float*)g_AO;
    float* __restrict__ C = pick_out(out_sel, ext_out);

    __shared__ float As[BK][BM + 4];  // [k][m], row stride 132 floats (16B-mult)
    __shared__ float Bs[BK][BN + 4];  // [k][n], row stride 68 floats

    const int tid = threadIdx.x;
    const int tx  = tid & 15;         // 0..15 -> n cols tx*4..+3
    const int ty  = tid >> 4;         // 0..15 -> m rows ty*8..+7
    const int m0  = blockIdx.y * BM;
    const int n0  = blockIdx.x * BN;

    float acc[8][4];
    #pragma unroll
    for (int i = 0; i < 8; i++)
        #pragma unroll
        for (int j = 0; j < 4; j++) acc[i][j] = 0.f;

    for (int k0 = 0; k0 < EMBED_DIM; k0 += BK) {
        // ---- load A tile (128x16): 512 float4, 2 per thread, transposed store
        #pragma unroll
        for (int i = 0; i < 2; i++) {
            int f  = tid + i * 256;          // 0..511
            int r  = f >> 2;                 // row 0..127
            int kc = (f & 3) * 4;            // k sub-chunk
            float4 v = *(const float4*)(A + (size_t)(m0 + r) * EMBED_DIM + k0 + kc);
            As[kc + 0][r] = v.x; As[kc + 1][r] = v.y;
            As[kc + 2][r] = v.z; As[kc + 3][r] = v.w;
        }
        // ---- load W tile (64x16): 256 float4, 1 per thread, transposed store
        {
            int r  = tid >> 2;               // row 0..63 (n)
            int kc = (tid & 3) * 4;
            float4 v = *(const float4*)(W + (size_t)(n0 + r) * EMBED_DIM + k0 + kc);
            Bs[kc + 0][r] = v.x; Bs[kc + 1][r] = v.y;
            Bs[kc + 2][r] = v.z; Bs[kc + 3][r] = v.w;
        }
        __syncthreads();

        #pragma unroll
        for (int kk = 0; kk < BK; kk++) {
            float4 a0 = *(const float4*)&As[kk][ty * 8];
            float4 a1 = *(const float4*)&As[kk][ty * 8 + 4];
            float4 b  = *(const float4*)&Bs[kk][tx * 4];
            float av[8] = {a0.x, a0.y, a0.z, a0.w, a1.x, a1.y, a1.z, a1.w};
            float bv[4] = {b.x, b.y, b.z, b.w};
            #pragma unroll
            for (int i = 0; i < 8; i++)
                #pragma unroll
                for (int j = 0; j < 4; j++)
                    acc[i][j] += av[i] * bv[j];
        }
        __syncthreads();
    }

    float4 bb = make_float4(0.f, 0.f, 0.f, 0.f);
    if (bias) bb = *(const float4*)(bias + n0 + tx * 4);

    #pragma unroll
    for (int i = 0; i < 8; i++) {
        int row = m0 + ty * 8 + i;
        float4 o = make_float4(acc[i][0] + bb.x, acc[i][1] + bb.y,
                               acc[i][2] + bb.z, acc[i][3] + bb.w);
        *(float4*)(C + (size_t)row * EMBED_DIM + n0 + tx * 4) = o;
    }
}

// =================================================================================
// Flash attention: per CTA one (batch,head, 64-q-row tile); stream K/V in 32-row
// tiles. 256 threads: tx=tid&15 -> 2 k-cols / 4 d-cols, ty=tid>>4 -> 4 q-rows.
// Online softmax with per-row state replicated across the 16-lane tx group
// (butterfly shfl reductions). Static smem = 44.0 KB.
// Reads g_Q/g_K/g_V directly, writes g_AO directly (no pointer plumbing).
// =================================================================================
#define AQ 64     // q rows per CTA
#define AK 32     // k rows per tile

__global__ void __launch_bounds__(256) attn_kernel(
    const int* __restrict__ mask)     // [N, L] (logical shape (N,1,1,L))
{
    const float* __restrict__ Q  = g_Q;
    const float* __restrict__ K  = g_K;
    const float* __restrict__ V  = g_V;
    float*       __restrict__ AO = g_AO;

    __shared__ float Qt[HEAD_DIM][AQ + 4];  // [d][q], pre-scaled by 1/8
    __shared__ float Kt[HEAD_DIM][AK + 2];  // [d][k], stride 34 floats (8B-mult)
    __shared__ float Vs[AK][HEAD_DIM + 4];  // [k][d]
    __shared__ float Pt[AK][AQ + 4];        // [k][q]
    __shared__ float mk[AK];                // 0 or -1e20 additive mask

    const int tid = threadIdx.x;
    const int tx  = tid & 15;
    const int ty  = tid >> 4;
    const int q0  = blockIdx.x * AQ;
    const int b   = blockIdx.y >> 4;
    const int h   = blockIdx.y & 15;
    const size_t base = (size_t)b * SEQ_LEN * EMBED_DIM + (size_t)h * HEAD_DIM;

    // ---- load Q tile (64x64), transpose + scale by 1/sqrt(Dh)=0.125
    #pragma unroll
    for (int i = 0; i < 4; i++) {
        int f  = tid + i * 256;              // 0..1023
        int r  = f >> 4;                     // q row 0..63
        int dc = (f & 15) * 4;               // d col
        float4 v = *(const float4*)(Q + base + (size_t)(q0 + r) * EMBED_DIM + dc);
        Qt[dc + 0][r] = v.x * 0.125f;
        Qt[dc + 1][r] = v.y * 0.125f;
        Qt[dc + 2][r] = v.z * 0.125f;
        Qt[dc + 3][r] = v.w * 0.125f;
    }

    float m_i[4], l_i[4], o[4][4];
    #pragma unroll
    for (int qi = 0; qi < 4; qi++) {
        m_i[qi] = -1e30f; l_i[qi] = 0.f;
        #pragma unroll
        for (int di = 0; di < 4; di++) o[qi][di] = 0.f;
    }

    for (int kt = 0; kt < SEQ_LEN; kt += AK) {
        __syncthreads();   // prior-iteration Pt/Vs reads done before overwrite
        // ---- load K (transposed) & V (natural): 32x64 each, 2 float4/thread each
        #pragma unroll
        for (int i = 0; i < 2; i++) {
            int f  = tid + i * 256;          // 0..511
            int r  = f >> 4;                 // k row 0..31
            int dc = (f & 15) * 4;
            float4 kv = *(const float4*)(K + base + (size_t)(kt + r) * EMBED_DIM + dc);
            Kt[dc + 0][r] = kv.x; Kt[dc + 1][r] = kv.y;
            Kt[dc + 2][r] = kv.z; Kt[dc + 3][r] = kv.w;
            float4 vv = *(const float4*)(V + base + (size_t)(kt + r) * EMBED_DIM + dc);
            *(float4*)&Vs[r][dc] = vv;
        }
        if (tid < AK)
            mk[tid] = (mask[b * SEQ_LEN + kt + tid] == 0) ? -1e20f : 0.f;
        __syncthreads();

        // ---- S = (Q/8) K^T  : 4q x 2k fragment per thread
        float s[4][2];
        #pragma unroll
        for (int qi = 0; qi < 4; qi++) { s[qi][0] = 0.f; s[qi][1] = 0.f; }
        #pragma unroll 8
        for (int d = 0; d < HEAD_DIM; d++) {
            float4 qv = *(const float4*)&Qt[d][ty * 4];
            float2 kv = *(const float2*)&Kt[d][tx * 2];
            s[0][0] += qv.x * kv.x;  s[0][1] += qv.x * kv.y;
            s[1][0] += qv.y * kv.x;  s[1][1] += qv.y * kv.y;
            s[2][0] += qv.z * kv.x;  s[2][1] += qv.z * kv.y;
            s[3][0] += qv.w * kv.x;  s[3][1] += qv.w * kv.y;
        }
        {
            float a0 = mk[tx * 2], a1 = mk[tx * 2 + 1];
            #pragma unroll
            for (int qi = 0; qi < 4; qi++) { s[qi][0] += a0; s[qi][1] += a1; }
        }

        // ---- online softmax (row state replicated across the 16-lane tx group)
        float p[4][2];
        #pragma unroll
        for (int qi = 0; qi < 4; qi++) {
            float tm = fmaxf(s[qi][0], s[qi][1]);
            #pragma unroll
            for (int off = 1; off < 16; off <<= 1)
                tm = fmaxf(tm, __shfl_xor_sync(0xffffffffu, tm, off));
            float mn    = fmaxf(m_i[qi], tm);
            float alpha = __expf(m_i[qi] - mn);
            m_i[qi] = mn;
            p[qi][0] = __expf(s[qi][0] - mn);
            p[qi][1] = __expf(s[qi][1] - mn);
            float rs = p[qi][0] + p[qi][1];
            #pragma unroll
            for (int off = 1; off < 16; off <<= 1)
                rs += __shfl_xor_sync(0xffffffffu, rs, off);
            l_i[qi] = l_i[qi] * alpha + rs;
            #pragma unroll
            for (int di = 0; di < 4; di++) o[qi][di] *= alpha;
        }

        // ---- write P transposed: Pt[k][q]
        #pragma unroll
        for (int ki = 0; ki < 2; ki++) {
            float4 pv = make_float4(p[0][ki], p[1][ki], p[2][ki], p[3][ki]);
            *(float4*)&Pt[tx * 2 + ki][ty * 4] = pv;
        }
        __syncthreads();

        // ---- O += P V : 4q x 4d fragment per thread
        #pragma unroll 8
        for (int k = 0; k < AK; k++) {
            float4 pv = *(const float4*)&Pt[k][ty * 4];
            float4 vv = *(const float4*)&Vs[k][tx * 4];
            o[0][0] += pv.x * vv.x; o[0][1] += pv.x * vv.y; o[0][2] += pv.x * vv.z; o[0][3] += pv.x * vv.w;
            o[1][0] += pv.y * vv.x; o[1][1] += pv.y * vv.y; o[1][2] += pv.y * vv.z; o[1][3] += pv.y * vv.w;
            o[2][0] += pv.z * vv.x; o[2][1] += pv.z * vv.y; o[2][2] += pv.z * vv.z; o[2][3] += pv.z * vv.w;
            o[3][0] += pv.w * vv.x; o[3][1] += pv.w * vv.y; o[3][2] += pv.w * vv.z; o[3][3] += pv.w * vv.w;
        }
    }

    // ---- epilogue: normalize and write AO[token][h*64 + d]
    #pragma unroll
    for (int qi = 0; qi < 4; qi++) {
        float inv = 1.f / l_i[qi];
        float4 ov = make_float4(o[qi][0] * inv, o[qi][1] * inv,
                                o[qi][2] * inv, o[qi][3] * inv);
        *(float4*)(AO + base + (size_t)(q0 + ty * 4 + qi) * EMBED_DIM + tx * 4) = ov;
    }
}

// =================================================================================
// kernel_launch: PURE kernel launches — no runtime API calls of any kind.
// =================================================================================
extern "C" void kernel_launch(void* const* d_in, const int* in_sizes, int n_in,
                              void* d_out, int out_size)
{
    const float* values = (const float*)d_in[0];
    const float* keys   = (const float*)d_in[1];
    const float* query  = (const float*)d_in[2];
    const int*   mask   = (const int*)  d_in[3];
    const float* W_q    = (const float*)d_in[4];
    const float* W_k    = (const float*)d_in[5];
    const float* W_v    = (const float*)d_in[6];
    const float* W_o    = (const float*)d_in[7];
    const float* b_o    = (const float*)d_in[8];
    float* out = (float*)d_out;

    dim3 ggrid(EMBED_DIM / BN, NTOK / BM);          // (16, 32) = 512 CTAs
    gemm_wt_kernel<<<ggrid, 256>>>(query,  W_q, nullptr, OUT_Q, nullptr);
    gemm_wt_kernel<<<ggrid, 256>>>(keys,   W_k, nullptr, OUT_K, nullptr);
    gemm_wt_kernel<<<ggrid, 256>>>(values, W_v, nullptr, OUT_V, nullptr);

    dim3 agrid(SEQ_LEN / AQ, 2 * 16);               // (32, 32) = 1024 CTAs
    attn_kernel<<<agrid, 256>>>(mask);

    // A == nullptr -> kernel reads g_AO (device-resolved)
    gemm_wt_kernel<<<ggrid, 256>>>(nullptr, W_o, b_o, OUT_EXT, out);
}

// round 6
// speedup vs baseline: 1.0489x; 1.0461x over previous
#include <cuda_runtime.h>
#include <cuda_bf16.h>

// Problem constants (fixed by reference): N=2, L=2048, EMBED=1024, HEADS=16, Dh=64
#define SEQ_LEN   2048
#define EMBED_DIM 1024
#define NTOK      4096          // N * L
#define HEAD_DIM  64

typedef unsigned long long ull;

// ---------------- packed fp32x2 helpers (B300 FFMA2 path) ----------------
__device__ __forceinline__ ull bcast2(float x) {
    ull r; asm("mov.b64 %0, {%1, %1};" : "=l"(r) : "f"(x)); return r;
}
__device__ __forceinline__ ull pack2(float lo, float hi) {
    ull r; asm("mov.b64 %0, {%1, %2};" : "=l"(r) : "f"(lo), "f"(hi)); return r;
}
__device__ __forceinline__ float2 unpack2(ull v) {
    float lo, hi; asm("mov.b64 {%0, %1}, %2;" : "=f"(lo), "=f"(hi) : "l"(v));
    return make_float2(lo, hi);
}
__device__ __forceinline__ void ffma2(ull& d, ull a, ull b) {
    asm("fma.rn.f32x2 %0, %1, %2, %0;" : "+l"(d) : "l"(a), "l"(b));
}
__device__ __forceinline__ ull add2(ull a, ull b) {
    ull r; asm("add.rn.f32x2 %0, %1, %2;" : "=l"(r) : "l"(a), "l"(b)); return r;
}
__device__ __forceinline__ ull mul2(ull a, ull b) {
    ull r; asm("mul.rn.f32x2 %0, %1, %2;" : "=l"(r) : "l"(a), "l"(b)); return r;
}

// ---------------- scratch (device globals: allocation-guard safe) ----------------
__device__ float g_Q [NTOK * EMBED_DIM];
__device__ float g_K [NTOK * EMBED_DIM];
__device__ float g_V [NTOK * EMBED_DIM];
__device__ float g_AO[NTOK * EMBED_DIM];

#define OUT_Q   0
#define OUT_K   1
#define OUT_V   2
#define OUT_EXT 4

__device__ __forceinline__ float* pick_out(int sel, float* ext) {
    switch (sel) {
        case OUT_Q:  return g_Q;
        case OUT_K:  return g_K;
        case OUT_V:  return g_V;
        default:     return ext;
    }
}

// =================================================================================
// GEMM:  C[M=4096, N=1024] = A[4096,1024] @ W[1024,1024]^T  (+ bias)
// Tile 128x128x16, 256 threads, thread computes 8m x 8n with f32x2 accumulators
// paired over n (B smem is n-consecutive -> zero-cost ull2 reinterpret; the 8
// A-broadcast packs per kk ride the ALU pipe).
// A_in == nullptr means "read g_AO" (device-resolved; keeps launch API-free).
// =================================================================================
#define BM 128
#define BN 128
#define BK 16

__global__ void __launch_bounds__(256) gemm_wt_kernel(
    const float* __restrict__ A_in,
    const float* __restrict__ W,
    const float* __restrict__ bias,   // may be nullptr
    int out_sel,
    float* ext_out)
{
    const float* __restrict__ A = A_in ? A_in : (const float*)g_AO;
    float* __restrict__ C = pick_out(out_sel, ext_out);

    __shared__ float As[BK][BM + 4];  // [k][m], row stride 132 floats = 528B (16B mult)
    __shared__ float Bs[BK][BN + 4];  // [k][n], row stride 132 floats

    const int tid = threadIdx.x;
    const int tx  = tid & 15;         // n block: cols tx*8 .. +7
    const int ty  = tid >> 4;         // m block: rows ty*8 .. +7
    const int m0  = blockIdx.y * BM;
    const int n0  = blockIdx.x * BN;

    ull acc2[8][4];                   // [m][n-pair], each holds (n, n+1)
    #pragma unroll
    for (int i = 0; i < 8; i++)
        #pragma unroll
        for (int j = 0; j < 4; j++) acc2[i][j] = 0ull;

    for (int k0 = 0; k0 < EMBED_DIM; k0 += BK) {
        // ---- load A tile (128x16): 512 float4, 2/thread, transposed store
        #pragma unroll
        for (int i = 0; i < 2; i++) {
            int f  = tid + i * 256;          // 0..511
            int r  = f >> 2;                 // row 0..127
            int kc = (f & 3) * 4;
            float4 v = *(const float4*)(A + (size_t)(m0 + r) * EMBED_DIM + k0 + kc);
            As[kc + 0][r] = v.x; As[kc + 1][r] = v.y;
            As[kc + 2][r] = v.z; As[kc + 3][r] = v.w;
        }
        // ---- load W tile (128x16): 512 float4, 2/thread, transposed store
        #pragma unroll
        for (int i = 0; i < 2; i++) {
            int f  = tid + i * 256;
            int r  = f >> 2;                 // row 0..127 (n)
            int kc = (f & 3) * 4;
            float4 v = *(const float4*)(W + (size_t)(n0 + r) * EMBED_DIM + k0 + kc);
            Bs[kc + 0][r] = v.x; Bs[kc + 1][r] = v.y;
            Bs[kc + 2][r] = v.z; Bs[kc + 3][r] = v.w;
        }
        __syncthreads();

        #pragma unroll
        for (int kk = 0; kk < BK; kk++) {
            float4 a0 = *(const float4*)&As[kk][ty * 8];
            float4 a1 = *(const float4*)&As[kk][ty * 8 + 4];
            ulonglong2 b0 = *(const ulonglong2*)&Bs[kk][tx * 8];
            ulonglong2 b1 = *(const ulonglong2*)&Bs[kk][tx * 8 + 4];
            ull ab[8] = { bcast2(a0.x), bcast2(a0.y), bcast2(a0.z), bcast2(a0.w),
                          bcast2(a1.x), bcast2(a1.y), bcast2(a1.z), bcast2(a1.w) };
            #pragma unroll
            for (int i = 0; i < 8; i++) {
                ffma2(acc2[i][0], ab[i], b0.x);
                ffma2(acc2[i][1], ab[i], b0.y);
                ffma2(acc2[i][2], ab[i], b1.x);
                ffma2(acc2[i][3], ab[i], b1.y);
            }
        }
        __syncthreads();
    }

    // ---- epilogue: packed bias add, 16B packed stores
    ull bb[4] = {0ull, 0ull, 0ull, 0ull};
    if (bias) {
        ulonglong2 t0 = *(const ulonglong2*)(bias + n0 + tx * 8);
        ulonglong2 t1 = *(const ulonglong2*)(bias + n0 + tx * 8 + 4);
        bb[0] = t0.x; bb[1] = t0.y; bb[2] = t1.x; bb[3] = t1.y;
    }
    #pragma unroll
    for (int i = 0; i < 8; i++) {
        int row = m0 + ty * 8 + i;
        ulonglong2 s0, s1;
        s0.x = add2(acc2[i][0], bb[0]); s0.y = add2(acc2[i][1], bb[1]);
        s1.x = add2(acc2[i][2], bb[2]); s1.y = add2(acc2[i][3], bb[3]);
        *(ulonglong2*)(C + (size_t)row * EMBED_DIM + n0 + tx * 8)     = s0;
        *(ulonglong2*)(C + (size_t)row * EMBED_DIM + n0 + tx * 8 + 4) = s1;
    }
}

// =================================================================================
// Flash attention: per CTA one (batch,head, 64-q-row tile); stream K/V in 32-row
// tiles. 256 threads: tx=tid&15 -> 2 k-cols / 4 d-cols, ty=tid>>4 -> 4 q-rows.
// S and PV inner loops use f32x2 paired over q (Qt/Pt are q-consecutive -> free
// ull2 pairs); K/V values broadcast-packed. Softmax scalar, unchanged.
// Static smem = 44.0 KB. Reads g_Q/g_K/g_V, writes g_AO.
// =================================================================================
#define AQ 64     // q rows per CTA
#define AK 32     // k rows per tile

__global__ void __launch_bounds__(256) attn_kernel(
    const int* __restrict__ mask)     // [N, L] (logical (N,1,1,L))
{
    const float* __restrict__ Q  = g_Q;
    const float* __restrict__ K  = g_K;
    const float* __restrict__ V  = g_V;
    float*       __restrict__ AO = g_AO;

    __shared__ float Qt[HEAD_DIM][AQ + 4];  // [d][q], pre-scaled by 1/8; stride 272B
    __shared__ float Kt[HEAD_DIM][AK + 2];  // [d][k], stride 136B (8B mult)
    __shared__ float Vs[AK][HEAD_DIM + 4];  // [k][d], stride 272B
    __shared__ float Pt[AK][AQ + 4];        // [k][q], stride 272B
    __shared__ float mk[AK];                // 0 or -1e20 additive mask

    const int tid = threadIdx.x;
    const int tx  = tid & 15;
    const int ty  = tid >> 4;
    const int q0  = blockIdx.x * AQ;
    const int b   = blockIdx.y >> 4;
    const int h   = blockIdx.y & 15;
    const size_t base = (size_t)b * SEQ_LEN * EMBED_DIM + (size_t)h * HEAD_DIM;

    // ---- load Q tile (64x64), transpose + scale by 1/sqrt(Dh)=0.125
    #pragma unroll
    for (int i = 0; i < 4; i++) {
        int f  = tid + i * 256;
        int r  = f >> 4;                     // q row 0..63
        int dc = (f & 15) * 4;
        float4 v = *(const float4*)(Q + base + (size_t)(q0 + r) * EMBED_DIM + dc);
        Qt[dc + 0][r] = v.x * 0.125f;
        Qt[dc + 1][r] = v.y * 0.125f;
        Qt[dc + 2][r] = v.z * 0.125f;
        Qt[dc + 3][r] = v.w * 0.125f;
    }

    float m_i[4], l_i[4];
    ull o2[2][4];                            // [q-pair][d], lanes = (q even, q odd)
    #pragma unroll
    for (int qi = 0; qi < 4; qi++) { m_i[qi] = -1e30f; l_i[qi] = 0.f; }
    #pragma unroll
    for (int qp = 0; qp < 2; qp++)
        #pragma unroll
        for (int di = 0; di < 4; di++) o2[qp][di] = 0ull;

    for (int kt = 0; kt < SEQ_LEN; kt += AK) {
        __syncthreads();   // prior-iteration Pt/Vs reads done before overwrite
        // ---- load K (transposed) & V (natural): 32x64 each, 2 float4/thread each
        #pragma unroll
        for (int i = 0; i < 2; i++) {
            int f  = tid + i * 256;
            int r  = f >> 4;                 // k row 0..31
            int dc = (f & 15) * 4;
            float4 kv = *(const float4*)(K + base + (size_t)(kt + r) * EMBED_DIM + dc);
            Kt[dc + 0][r] = kv.x; Kt[dc + 1][r] = kv.y;
            Kt[dc + 2][r] = kv.z; Kt[dc + 3][r] = kv.w;
            float4 vv = *(const float4*)(V + base + (size_t)(kt + r) * EMBED_DIM + dc);
            *(float4*)&Vs[r][dc] = vv;
        }
        if (tid < AK)
            mk[tid] = (mask[b * SEQ_LEN + kt + tid] == 0) ? -1e20f : 0.f;
        __syncthreads();

        // ---- S = (Q/8) K^T : f32x2 over q-pairs, 4 FFMA2/d (was 8 FFMA)
        ull s2[2][2];                        // [q-pair][k]
        s2[0][0] = 0ull; s2[0][1] = 0ull; s2[1][0] = 0ull; s2[1][1] = 0ull;
        #pragma unroll 8
        for (int d = 0; d < HEAD_DIM; d++) {
            ulonglong2 q2 = *(const ulonglong2*)&Qt[d][ty * 4];   // (q0,q1),(q2,q3)
            float2 kv = *(const float2*)&Kt[d][tx * 2];
            ull k0 = bcast2(kv.x), k1 = bcast2(kv.y);
            ffma2(s2[0][0], q2.x, k0);  ffma2(s2[0][1], q2.x, k1);
            ffma2(s2[1][0], q2.y, k0);  ffma2(s2[1][1], q2.y, k1);
        }
        // unpack to scalars for softmax
        float s[4][2];
        {
            float2 u;
            u = unpack2(s2[0][0]); s[0][0] = u.x; s[1][0] = u.y;
            u = unpack2(s2[0][1]); s[0][1] = u.x; s[1][1] = u.y;
            u = unpack2(s2[1][0]); s[2][0] = u.x; s[3][0] = u.y;
            u = unpack2(s2[1][1]); s[2][1] = u.x; s[3][1] = u.y;
        }
        {
            float a0 = mk[tx * 2], a1 = mk[tx * 2 + 1];
            #pragma unroll
            for (int qi = 0; qi < 4; qi++) { s[qi][0] += a0; s[qi][1] += a1; }
        }

        // ---- online softmax (row state replicated across the 16-lane tx group)
        float p[4][2], alpha[4];
        #pragma unroll
        for (int qi = 0; qi < 4; qi++) {
            float tm = fmaxf(s[qi][0], s[qi][1]);
            #pragma unroll
            for (int off = 1; off < 16; off <<= 1)
                tm = fmaxf(tm, __shfl_xor_sync(0xffffffffu, tm, off));
            float mn = fmaxf(m_i[qi], tm);
            alpha[qi] = __expf(m_i[qi] - mn);
            m_i[qi] = mn;
            p[qi][0] = __expf(s[qi][0] - mn);
            p[qi][1] = __expf(s[qi][1] - mn);
            float rs = p[qi][0] + p[qi][1];
            #pragma unroll
            for (int off = 1; off < 16; off <<= 1)
                rs += __shfl_xor_sync(0xffffffffu, rs, off);
            l_i[qi] = l_i[qi] * alpha[qi] + rs;
        }
        // packed alpha rescale of o
        {
            ull am0 = pack2(alpha[0], alpha[1]);
            ull am1 = pack2(alpha[2], alpha[3]);
            #pragma unroll
            for (int di = 0; di < 4; di++) {
                o2[0][di] = mul2(o2[0][di], am0);
                o2[1][di] = mul2(o2[1][di], am1);
            }
        }

        // ---- write P transposed: Pt[k][q]
        #pragma unroll
        for (int ki = 0; ki < 2; ki++) {
            float4 pv = make_float4(p[0][ki], p[1][ki], p[2][ki], p[3][ki]);
            *(float4*)&Pt[tx * 2 + ki][ty * 4] = pv;
        }
        __syncthreads();

        // ---- O += P V : f32x2 over q-pairs, 8 FFMA2/k (was 16 FFMA)
        #pragma unroll 4
        for (int k = 0; k < AK; k++) {
            ulonglong2 p2 = *(const ulonglong2*)&Pt[k][ty * 4];   // (q0,q1),(q2,q3)
            float4 vv = *(const float4*)&Vs[k][tx * 4];
            ull v0 = bcast2(vv.x), v1 = bcast2(vv.y), v2 = bcast2(vv.z), v3 = bcast2(vv.w);
            ffma2(o2[0][0], p2.x, v0); ffma2(o2[0][1], p2.x, v1);
            ffma2(o2[0][2], p2.x, v2); ffma2(o2[0][3], p2.x, v3);
            ffma2(o2[1][0], p2.y, v0); ffma2(o2[1][1], p2.y, v1);
            ffma2(o2[1][2], p2.y, v2); ffma2(o2[1][3], p2.y, v3);
        }
    }

    // ---- epilogue: normalize and write AO[token][h*64 + d]
    #pragma unroll
    for (int qp = 0; qp < 2; qp++) {
        float2 u0 = unpack2(o2[qp][0]);
        float2 u1 = unpack2(o2[qp][1]);
        float2 u2 = unpack2(o2[qp][2]);
        float2 u3 = unpack2(o2[qp][3]);
        int qa = 2 * qp, qb = 2 * qp + 1;
        float ia = 1.f / l_i[qa], ib = 1.f / l_i[qb];
        float4 ra = make_float4(u0.x * ia, u1.x * ia, u2.x * ia, u3.x * ia);
        float4 rb = make_float4(u0.y * ib, u1.y * ib, u2.y * ib, u3.y * ib);
        *(float4*)(AO + base + (size_t)(q0 + ty * 4 + qa) * EMBED_DIM + tx * 4) = ra;
        *(float4*)(AO + base + (size_t)(q0 + ty * 4 + qb) * EMBED_DIM + tx * 4) = rb;
    }
}

// =================================================================================
// kernel_launch: PURE kernel launches — no runtime API calls of any kind.
// =================================================================================
extern "C" void kernel_launch(void* const* d_in, const int* in_sizes, int n_in,
                              void* d_out, int out_size)
{
    const float* values = (const float*)d_in[0];
    const float* keys   = (const float*)d_in[1];
    const float* query  = (const float*)d_in[2];
    const int*   mask   = (const int*)  d_in[3];
    const float* W_q    = (const float*)d_in[4];
    const float* W_k    = (const float*)d_in[5];
    const float* W_v    = (const float*)d_in[6];
    const float* W_o    = (const float*)d_in[7];
    const float* b_o    = (const float*)d_in[8];
    float* out = (float*)d_out;

    dim3 ggrid(EMBED_DIM / BN, NTOK / BM);          // (8, 32) = 256 CTAs, one wave
    gemm_wt_kernel<<<ggrid, 256>>>(query,  W_q, nullptr, OUT_Q, nullptr);
    gemm_wt_kernel<<<ggrid, 256>>>(keys,   W_k, nullptr, OUT_K, nullptr);
    gemm_wt_kernel<<<ggrid, 256>>>(values, W_v, nullptr, OUT_V, nullptr);

    dim3 agrid(SEQ_LEN / AQ, 2 * 16);               // (32, 32) = 1024 CTAs
    attn_kernel<<<agrid, 256>>>(mask);

    // A == nullptr -> kernel reads g_AO (device-resolved)
    gemm_wt_kernel<<<ggrid, 256>>>(nullptr, W_o, b_o, OUT_EXT, out);
}

// round 8
// speedup vs baseline: 1.4014x; 1.3360x over previous
#include <cuda_runtime.h>
#include <cuda_bf16.h>
#include <cstdint>

// Problem constants: N=2, L=2048, EMBED=1024, HEADS=16, Dh=64
#define SEQ_LEN   2048
#define EMBED_DIM 1024
#define NTOK      4096
#define HEAD_DIM  64

typedef unsigned long long ull;

// ---------------- packed fp32x2 helpers (attention) ----------------
__device__ __forceinline__ ull bcast2(float x) {
    ull r; asm("mov.b64 %0, {%1, %1};" : "=l"(r) : "f"(x)); return r;
}
__device__ __forceinline__ ull pack2(float lo, float hi) {
    ull r; asm("mov.b64 %0, {%1, %2};" : "=l"(r) : "f"(lo), "f"(hi)); return r;
}
__device__ __forceinline__ float2 unpack2(ull v) {
    float lo, hi; asm("mov.b64 {%0, %1}, %2;" : "=f"(lo), "=f"(hi) : "l"(v));
    return make_float2(lo, hi);
}
__device__ __forceinline__ void ffma2(ull& d, ull a, ull b) {
    asm("fma.rn.f32x2 %0, %1, %2, %0;" : "+l"(d) : "l"(a), "l"(b));
}
__device__ __forceinline__ ull mul2(ull a, ull b) {
    ull r; asm("mul.rn.f32x2 %0, %1, %2;" : "=l"(r) : "l"(a), "l"(b)); return r;
}

// ---------------- warp-MMA helpers (baseline PTX: no 'a'-suffix features) ----------
__device__ __forceinline__ uint32_t smem_u32(const void* p) {
    uint32_t a;
    asm("{ .reg .u64 t; cvta.to.shared.u64 t, %1; cvt.u32.u64 %0, t; }"
        : "=r"(a) : "l"(p));
    return a;
}
__device__ __forceinline__ void ldm_x4(uint32_t& r0, uint32_t& r1,
                                       uint32_t& r2, uint32_t& r3, uint32_t addr) {
    asm volatile("ldmatrix.sync.aligned.m8n8.x4.shared.b16 {%0,%1,%2,%3}, [%4];"
                 : "=r"(r0), "=r"(r1), "=r"(r2), "=r"(r3) : "r"(addr));
}
__device__ __forceinline__ void mma16816(float* c, const uint32_t* a, const uint32_t* b) {
    asm volatile(
        "mma.sync.aligned.m16n8k16.row.col.f32.bf16.bf16.f32 "
        "{%0,%1,%2,%3}, {%4,%5,%6,%7}, {%8,%9}, {%0,%1,%2,%3};"
        : "+f"(c[0]), "+f"(c[1]), "+f"(c[2]), "+f"(c[3])
        : "r"(a[0]), "r"(a[1]), "r"(a[2]), "r"(a[3]), "r"(b[0]), "r"(b[1]));
}

// ---------------- scratch (device globals: allocation-guard safe) ----------------
__device__ float g_Q [NTOK * EMBED_DIM];
__device__ float g_K [NTOK * EMBED_DIM];
__device__ float g_V [NTOK * EMBED_DIM];
__device__ float g_AO[NTOK * EMBED_DIM];
__device__ __nv_bfloat16 g_Ahi[NTOK * EMBED_DIM];
__device__ __nv_bfloat16 g_Alo[NTOK * EMBED_DIM];
__device__ __nv_bfloat16 g_Whi[EMBED_DIM * EMBED_DIM];
__device__ __nv_bfloat16 g_Wlo[EMBED_DIM * EMBED_DIM];

#define OUT_Q   0
#define OUT_K   1
#define OUT_V   2
#define OUT_EXT 4

__device__ __forceinline__ float* pick_out(int sel, float* ext) {
    switch (sel) {
        case OUT_Q:  return g_Q;
        case OUT_K:  return g_K;
        case OUT_V:  return g_V;
        default:     return ext;
    }
}

// =================================================================================
// split_kernel: fp32 -> (hi bf16, lo bf16), x = hi + lo + O(2^-17 x).
// dst==0 -> g_Ahi/g_Alo ; dst==1 -> g_Whi/g_Wlo. x_in==nullptr -> read g_AO.
// =================================================================================
__global__ void __launch_bounds__(256) split_kernel(
    const float* __restrict__ x_in, int dst, int n4)
{
    const float* __restrict__ x = x_in ? x_in : (const float*)g_AO;
    __nv_bfloat16* __restrict__ hi = dst ? g_Whi : g_Ahi;
    __nv_bfloat16* __restrict__ lo = dst ? g_Wlo : g_Alo;
    int i = blockIdx.x * blockDim.x + threadIdx.x;
    if (i >= n4) return;
    float4 v = ((const float4*)x)[i];
    __nv_bfloat16 h0 = __float2bfloat16(v.x), h1 = __float2bfloat16(v.y);
    __nv_bfloat16 h2 = __float2bfloat16(v.z), h3 = __float2bfloat16(v.w);
    __nv_bfloat16 l0 = __float2bfloat16(v.x - __bfloat162float(h0));
    __nv_bfloat16 l1 = __float2bfloat16(v.y - __bfloat162float(h1));
    __nv_bfloat16 l2 = __float2bfloat16(v.z - __bfloat162float(h2));
    __nv_bfloat16 l3 = __float2bfloat16(v.w - __bfloat162float(h3));
    uint2 H, L;
    H.x = (uint32_t)__bfloat16_as_ushort(h0) | ((uint32_t)__bfloat16_as_ushort(h1) << 16);
    H.y = (uint32_t)__bfloat16_as_ushort(h2) | ((uint32_t)__bfloat16_as_ushort(h3) << 16);
    L.x = (uint32_t)__bfloat16_as_ushort(l0) | ((uint32_t)__bfloat16_as_ushort(l1) << 16);
    L.y = (uint32_t)__bfloat16_as_ushort(l2) | ((uint32_t)__bfloat16_as_ushort(l3) << 16);
    ((uint2*)hi)[i] = H;
    ((uint2*)lo)[i] = L;
}

// =================================================================================
// Tensor-core GEMM via mma.sync m16n8k16 bf16 (bf16x3 split: hihi + lohi + hilo).
// C[4096,1024] = A @ W^T (+bias).  CTA tile 128m x 128n, K-chunks of 32.
// 256 threads = 8 warps; warp tile 32m x 64n = 2 m-frags x 8 n-frags.
// smem row stride 40 bf16 (80B) -> ldmatrix reads are bank-conflict-free.
// =================================================================================
#define GBM 128
#define GBN 128
#define GKC 32
#define GST 40      // bf16 elements per smem row

__global__ void __launch_bounds__(256) gemm_mma_kernel(
    const float* __restrict__ bias,   // may be nullptr
    int out_sel,
    float* ext_out)
{
    float* __restrict__ C = pick_out(out_sel, ext_out);

    __shared__ __nv_bfloat16 sAhi[GBM * GST];
    __shared__ __nv_bfloat16 sAlo[GBM * GST];
    __shared__ __nv_bfloat16 sBhi[GBN * GST];
    __shared__ __nv_bfloat16 sBlo[GBN * GST];

    const int tid  = threadIdx.x;
    const int lane = tid & 31;
    const int wid  = tid >> 5;
    const int wm0  = (wid & 3) * 32;      // warp m offset in CTA tile
    const int wn0  = (wid >> 2) * 64;     // warp n offset
    const int m0   = blockIdx.y * GBM;
    const int n0   = blockIdx.x * GBN;

    // ldmatrix lane->address components (PTX ISA fragment layouts)
    const int a_r  = lane & 15;           // A: row within 16-row frag
    const int a_c8 = (lane >> 4) << 3;    // A: k-half (0 or 8)
    const int b_r  = (lane & 7) + (((lane >> 4) & 1) << 3);  // B: n row (+8 for lanes>=16)
    const int b_c8 = ((lane >> 3) & 1) << 3;                 // B: k-half (odd octet -> +8)

    float acc[2][8][4];
    #pragma unroll
    for (int mi = 0; mi < 2; mi++)
        #pragma unroll
        for (int ni = 0; ni < 8; ni++)
            #pragma unroll
            for (int r = 0; r < 4; r++) acc[mi][ni][r] = 0.f;

    for (int kb = 0; kb < EMBED_DIM; kb += GKC) {
        __syncthreads();   // prior-iteration ldmatrix reads done before overwrite
        // ---- stage 4 tiles (A hi/lo: 128x32, B=W hi/lo: 128x32), 2 uint4/thread each
        #pragma unroll
        for (int i = 0; i < 2; i++) {
            int f  = tid + (i << 8);      // 0..511
            int r  = f >> 2;              // row 0..127
            int ck = (f & 3) * 8;         // k sub-chunk (bf16 units)
            size_t ga = (size_t)(m0 + r) * EMBED_DIM + kb + ck;
            size_t gb = (size_t)(n0 + r) * EMBED_DIM + kb + ck;
            uint32_t so = (uint32_t)(r * GST + ck);
            *(uint4*)&sAhi[so] = *(const uint4*)&g_Ahi[ga];
            *(uint4*)&sAlo[so] = *(const uint4*)&g_Alo[ga];
            *(uint4*)&sBhi[so] = *(const uint4*)&g_Whi[gb];
            *(uint4*)&sBlo[so] = *(const uint4*)&g_Wlo[gb];
        }
        __syncthreads();

        #pragma unroll
        for (int kk = 0; kk < GKC; kk += 16) {
            uint32_t ah[2][4], al[2][4], bb[8][2];
            // A hi & lo fragments (2x ldmatrix.x4 each)
            #pragma unroll
            for (int mi = 0; mi < 2; mi++) {
                uint32_t ad = smem_u32(&sAhi[(wm0 + mi * 16 + a_r) * GST + kk + a_c8]);
                ldm_x4(ah[mi][0], ah[mi][1], ah[mi][2], ah[mi][3], ad);
                ad = smem_u32(&sAlo[(wm0 + mi * 16 + a_r) * GST + kk + a_c8]);
                ldm_x4(al[mi][0], al[mi][1], al[mi][2], al[mi][3], ad);
            }
            // B hi fragments: 4x ldmatrix.x4 -> 8 n-frags (regs: [2np]={kL,kH}, [2np+1]={kL,kH})
            #pragma unroll
            for (int np = 0; np < 4; np++) {
                uint32_t ad = smem_u32(&sBhi[(wn0 + np * 16 + b_r) * GST + kk + b_c8]);
                ldm_x4(bb[2 * np][0], bb[2 * np][1], bb[2 * np + 1][0], bb[2 * np + 1][1], ad);
            }
            #pragma unroll
            for (int mi = 0; mi < 2; mi++)
                #pragma unroll
                for (int ni = 0; ni < 8; ni++) mma16816(acc[mi][ni], ah[mi], bb[ni]);
            #pragma unroll
            for (int mi = 0; mi < 2; mi++)
                #pragma unroll
                for (int ni = 0; ni < 8; ni++) mma16816(acc[mi][ni], al[mi], bb[ni]);
            // B lo fragments overwrite bb; third product Ahi x Wlo
            #pragma unroll
            for (int np = 0; np < 4; np++) {
                uint32_t ad = smem_u32(&sBlo[(wn0 + np * 16 + b_r) * GST + kk + b_c8]);
                ldm_x4(bb[2 * np][0], bb[2 * np][1], bb[2 * np + 1][0], bb[2 * np + 1][1], ad);
            }
            #pragma unroll
            for (int mi = 0; mi < 2; mi++)
                #pragma unroll
                for (int ni = 0; ni < 8; ni++) mma16816(acc[mi][ni], ah[mi], bb[ni]);
        }
    }

    // ---- epilogue: C frag map: c0,c1 -> (row=lane>>2, col=2*(lane&3)); c2,c3 -> row+8
    const int er = lane >> 2;
    const int ec = (lane & 3) * 2;
    #pragma unroll
    for (int mi = 0; mi < 2; mi++) {
        #pragma unroll
        for (int ni = 0; ni < 8; ni++) {
            int row = m0 + wm0 + mi * 16 + er;
            int col = n0 + wn0 + ni * 8 + ec;
            float b0 = 0.f, b1 = 0.f;
            if (bias) { b0 = bias[col]; b1 = bias[col + 1]; }
            *(float2*)&C[(size_t)row * EMBED_DIM + col] =
                make_float2(acc[mi][ni][0] + b0, acc[mi][ni][1] + b1);
            *(float2*)&C[(size_t)(row + 8) * EMBED_DIM + col] =
                make_float2(acc[mi][ni][2] + b0, acc[mi][ni][3] + b1);
        }
    }
}

// =================================================================================
// Flash attention — UNCHANGED from passing R6 kernel (1072us launch).
// =================================================================================
#define AQ 64
#define AK 32

__global__ void __launch_bounds__(256) attn_kernel(
    const int* __restrict__ mask)
{
    const float* __restrict__ Q  = g_Q;
    const float* __restrict__ K  = g_K;
    const float* __restrict__ V  = g_V;
    float*       __restrict__ AO = g_AO;

    __shared__ float Qt[HEAD_DIM][AQ + 4];
    __shared__ float Kt[HEAD_DIM][AK + 2];
    __shared__ float Vs[AK][HEAD_DIM + 4];
    __shared__ float Pt[AK][AQ + 4];
    __shared__ float mk[AK];

    const int tid = threadIdx.x;
    const int tx  = tid & 15;
    const int ty  = tid >> 4;
    const int q0  = blockIdx.x * AQ;
    const int b   = blockIdx.y >> 4;
    const int h   = blockIdx.y & 15;
    const size_t base = (size_t)b * SEQ_LEN * EMBED_DIM + (size_t)h * HEAD_DIM;

    #pragma unroll
    for (int i = 0; i < 4; i++) {
        int f  = tid + i * 256;
        int r  = f >> 4;
        int dc = (f & 15) * 4;
        float4 v = *(const float4*)(Q + base + (size_t)(q0 + r) * EMBED_DIM + dc);
        Qt[dc + 0][r] = v.x * 0.125f;
        Qt[dc + 1][r] = v.y * 0.125f;
        Qt[dc + 2][r] = v.z * 0.125f;
        Qt[dc + 3][r] = v.w * 0.125f;
    }

    float m_i[4], l_i[4];
    ull o2[2][4];
    #pragma unroll
    for (int qi = 0; qi < 4; qi++) { m_i[qi] = -1e30f; l_i[qi] = 0.f; }
    #pragma unroll
    for (int qp = 0; qp < 2; qp++)
        #pragma unroll
        for (int di = 0; di < 4; di++) o2[qp][di] = 0ull;

    for (int kt = 0; kt < SEQ_LEN; kt += AK) {
        __syncthreads();
        #pragma unroll
        for (int i = 0; i < 2; i++) {
            int f  = tid + i * 256;
            int r  = f >> 4;
            int dc = (f & 15) * 4;
            float4 kv = *(const float4*)(K + base + (size_t)(kt + r) * EMBED_DIM + dc);
            Kt[dc + 0][r] = kv.x; Kt[dc + 1][r] = kv.y;
            Kt[dc + 2][r] = kv.z; Kt[dc + 3][r] = kv.w;
            float4 vv = *(const float4*)(V + base + (size_t)(kt + r) * EMBED_DIM + dc);
            *(float4*)&Vs[r][dc] = vv;
        }
        if (tid < AK)
            mk[tid] = (mask[b * SEQ_LEN + kt + tid] == 0) ? -1e20f : 0.f;
        __syncthreads();

        ull s2[2][2];
        s2[0][0] = 0ull; s2[0][1] = 0ull; s2[1][0] = 0ull; s2[1][1] = 0ull;
        #pragma unroll 8
        for (int d = 0; d < HEAD_DIM; d++) {
            ulonglong2 q2 = *(const ulonglong2*)&Qt[d][ty * 4];
            float2 kv = *(const float2*)&Kt[d][tx * 2];
            ull k0 = bcast2(kv.x), k1 = bcast2(kv.y);
            ffma2(s2[0][0], q2.x, k0);  ffma2(s2[0][1], q2.x, k1);
            ffma2(s2[1][0], q2.y, k0);  ffma2(s2[1][1], q2.y, k1);
        }
        float s[4][2];
        {
            float2 u;
            u = unpack2(s2[0][0]); s[0][0] = u.x; s[1][0] = u.y;
            u = unpack2(s2[0][1]); s[0][1] = u.x; s[1][1] = u.y;
            u = unpack2(s2[1][0]); s[2][0] = u.x; s[3][0] = u.y;
            u = unpack2(s2[1][1]); s[2][1] = u.x; s[3][1] = u.y;
        }
        {
            float a0 = mk[tx * 2], a1 = mk[tx * 2 + 1];
            #pragma unroll
            for (int qi = 0; qi < 4; qi++) { s[qi][0] += a0; s[qi][1] += a1; }
        }

        float p[4][2], alpha[4];
        #pragma unroll
        for (int qi = 0; qi < 4; qi++) {
            float tm = fmaxf(s[qi][0], s[qi][1]);
            #pragma unroll
            for (int off = 1; off < 16; off <<= 1)
                tm = fmaxf(tm, __shfl_xor_sync(0xffffffffu, tm, off));
            float mn = fmaxf(m_i[qi], tm);
            alpha[qi] = __expf(m_i[qi] - mn);
            m_i[qi] = mn;
            p[qi][0] = __expf(s[qi][0] - mn);
            p[qi][1] = __expf(s[qi][1] - mn);
            float rs = p[qi][0] + p[qi][1];
            #pragma unroll
            for (int off = 1; off < 16; off <<= 1)
                rs += __shfl_xor_sync(0xffffffffu, rs, off);
            l_i[qi] = l_i[qi] * alpha[qi] + rs;
        }
        {
            ull am0 = pack2(alpha[0], alpha[1]);
            ull am1 = pack2(alpha[2], alpha[3]);
            #pragma unroll
            for (int di = 0; di < 4; di++) {
                o2[0][di] = mul2(o2[0][di], am0);
                o2[1][di] = mul2(o2[1][di], am1);
            }
        }

        #pragma unroll
        for (int ki = 0; ki < 2; ki++) {
            float4 pv = make_float4(p[0][ki], p[1][ki], p[2][ki], p[3][ki]);
            *(float4*)&Pt[tx * 2 + ki][ty * 4] = pv;
        }
        __syncthreads();

        #pragma unroll 4
        for (int k = 0; k < AK; k++) {
            ulonglong2 p2 = *(const ulonglong2*)&Pt[k][ty * 4];
            float4 vv = *(const float4*)&Vs[k][tx * 4];
            ull v0 = bcast2(vv.x), v1 = bcast2(vv.y), v2 = bcast2(vv.z), v3 = bcast2(vv.w);
            ffma2(o2[0][0], p2.x, v0); ffma2(o2[0][1], p2.x, v1);
            ffma2(o2[0][2], p2.x, v2); ffma2(o2[0][3], p2.x, v3);
            ffma2(o2[1][0], p2.y, v0); ffma2(o2[1][1], p2.y, v1);
            ffma2(o2[1][2], p2.y, v2); ffma2(o2[1][3], p2.y, v3);
        }
    }

    #pragma unroll
    for (int qp = 0; qp < 2; qp++) {
        float2 u0 = unpack2(o2[qp][0]);
        float2 u1 = unpack2(o2[qp][1]);
        float2 u2 = unpack2(o2[qp][2]);
        float2 u3 = unpack2(o2[qp][3]);
        int qa = 2 * qp, qb = 2 * qp + 1;
        float ia = 1.f / l_i[qa], ib = 1.f / l_i[qb];
        float4 ra = make_float4(u0.x * ia, u1.x * ia, u2.x * ia, u3.x * ia);
        float4 rb = make_float4(u0.y * ib, u1.y * ib, u2.y * ib, u3.y * ib);
        *(float4*)(AO + base + (size_t)(q0 + ty * 4 + qa) * EMBED_DIM + tx * 4) = ra;
        *(float4*)(AO + base + (size_t)(q0 + ty * 4 + qb) * EMBED_DIM + tx * 4) = rb;
    }
}

// =================================================================================
// kernel_launch: PURE kernel launches — no runtime API calls.
// =================================================================================
extern "C" void kernel_launch(void* const* d_in, const int* in_sizes, int n_in,
                              void* d_out, int out_size)
{
    const float* values = (const float*)d_in[0];
    const float* keys   = (const float*)d_in[1];
    const float* query  = (const float*)d_in[2];
    const int*   mask   = (const int*)  d_in[3];
    const float* W_q    = (const float*)d_in[4];
    const float* W_k    = (const float*)d_in[5];
    const float* W_v    = (const float*)d_in[6];
    const float* W_o    = (const float*)d_in[7];
    const float* b_o    = (const float*)d_in[8];
    float* out = (float*)d_out;

    const int nA4 = NTOK * EMBED_DIM / 4;         // 1,048,576
    const int nW4 = EMBED_DIM * EMBED_DIM / 4;    //   262,144
    dim3 tgrid(EMBED_DIM / GBN, NTOK / GBM);      // (8, 32) = 256 CTAs

    split_kernel<<<nA4 / 256, 256>>>(query, 0, nA4);
    split_kernel<<<nW4 / 256, 256>>>(W_q,   1, nW4);
    gemm_mma_kernel<<<tgrid, 256>>>(nullptr, OUT_Q, nullptr);

    split_kernel<<<nA4 / 256, 256>>>(keys,  0, nA4);
    split_kernel<<<nW4 / 256, 256>>>(W_k,   1, nW4);
    gemm_mma_kernel<<<tgrid, 256>>>(nullptr, OUT_K, nullptr);

    split_kernel<<<nA4 / 256, 256>>>(values, 0, nA4);
    split_kernel<<<nW4 / 256, 256>>>(W_v,    1, nW4);
    gemm_mma_kernel<<<tgrid, 256>>>(nullptr, OUT_V, nullptr);

    dim3 agrid(SEQ_LEN / AQ, 2 * 16);             // 1024 CTAs
    attn_kernel<<<agrid, 256>>>(mask);

    split_kernel<<<nA4 / 256, 256>>>(nullptr, 0, nA4);   // A = g_AO
    split_kernel<<<nW4 / 256, 256>>>(W_o,     1, nW4);
    gemm_mma_kernel<<<tgrid, 256>>>(b_o, OUT_EXT, out);
}

// round 9
// speedup vs baseline: 1.4541x; 1.0376x over previous
#include <cuda_runtime.h>
#include <cuda_bf16.h>
#include <cstdint>

// Problem constants: N=2, L=2048, EMBED=1024, HEADS=16, Dh=64
#define SEQ_LEN   2048
#define EMBED_DIM 1024
#define NTOK      4096
#define HEAD_DIM  64

// ---------------- warp-MMA helpers (baseline PTX; verified in R8) ----------------
__device__ __forceinline__ uint32_t smem_u32(const void* p) {
    uint32_t a;
    asm("{ .reg .u64 t; cvta.to.shared.u64 t, %1; cvt.u32.u64 %0, t; }"
        : "=r"(a) : "l"(p));
    return a;
}
__device__ __forceinline__ void ldm_x4(uint32_t& r0, uint32_t& r1,
                                       uint32_t& r2, uint32_t& r3, uint32_t addr) {
    asm volatile("ldmatrix.sync.aligned.m8n8.x4.shared.b16 {%0,%1,%2,%3}, [%4];"
                 : "=r"(r0), "=r"(r1), "=r"(r2), "=r"(r3) : "r"(addr));
}
__device__ __forceinline__ void mma16816(float* c, const uint32_t* a, const uint32_t* b) {
    asm volatile(
        "mma.sync.aligned.m16n8k16.row.col.f32.bf16.bf16.f32 "
        "{%0,%1,%2,%3}, {%4,%5,%6,%7}, {%8,%9}, {%0,%1,%2,%3};"
        : "+f"(c[0]), "+f"(c[1]), "+f"(c[2]), "+f"(c[3])
        : "r"(a[0]), "r"(a[1]), "r"(a[2]), "r"(a[3]), "r"(b[0]), "r"(b[1]));
}

// pack two floats' bf16-hi parts into one u32; and their lo-residues into another
__device__ __forceinline__ uint32_t bfpack(float a, float b) {
    return (uint32_t)__bfloat16_as_ushort(__float2bfloat16(a))
         | ((uint32_t)__bfloat16_as_ushort(__float2bfloat16(b)) << 16);
}
__device__ __forceinline__ void split2(float a, float b, uint32_t& h, uint32_t& l) {
    __nv_bfloat16 ha = __float2bfloat16(a), hb = __float2bfloat16(b);
    __nv_bfloat16 la = __float2bfloat16(a - __bfloat162float(ha));
    __nv_bfloat16 lb = __float2bfloat16(b - __bfloat162float(hb));
    h = (uint32_t)__bfloat16_as_ushort(ha) | ((uint32_t)__bfloat16_as_ushort(hb) << 16);
    l = (uint32_t)__bfloat16_as_ushort(la) | ((uint32_t)__bfloat16_as_ushort(lb) << 16);
}

// ---------------- scratch (device globals: allocation-guard safe) ----------------
__device__ __nv_bfloat16 g_Ahi [NTOK * EMBED_DIM];   // GEMM A operand (split input / attn out)
__device__ __nv_bfloat16 g_Alo [NTOK * EMBED_DIM];
__device__ __nv_bfloat16 g_Whi [EMBED_DIM * EMBED_DIM];
__device__ __nv_bfloat16 g_Wlo [EMBED_DIM * EMBED_DIM];
__device__ __nv_bfloat16 g_Qhi [NTOK * EMBED_DIM];   // [token][emb], pre-scaled by 0.125
__device__ __nv_bfloat16 g_Qlo [NTOK * EMBED_DIM];
__device__ __nv_bfloat16 g_Khi [NTOK * EMBED_DIM];   // [token][emb]
__device__ __nv_bfloat16 g_Klo [NTOK * EMBED_DIM];
__device__ __nv_bfloat16 g_Vthi[NTOK * EMBED_DIM];   // [bh][d][token]  (transposed!)
__device__ __nv_bfloat16 g_Vtlo[NTOK * EMBED_DIM];

#define OUT_Q   0
#define OUT_K   1
#define OUT_V   2
#define OUT_EXT 4

// =================================================================================
// split_kernel: fp32 -> (hi bf16, lo bf16). dst==0 -> g_Ahi/g_Alo ; dst==1 -> g_Whi/g_Wlo
// =================================================================================
__global__ void __launch_bounds__(256) split_kernel(
    const float* __restrict__ x, int dst, int n4)
{
    __nv_bfloat16* __restrict__ hi = dst ? g_Whi : g_Ahi;
    __nv_bfloat16* __restrict__ lo = dst ? g_Wlo : g_Alo;
    int i = blockIdx.x * blockDim.x + threadIdx.x;
    if (i >= n4) return;
    float4 v = ((const float4*)x)[i];
    uint2 H, L;
    split2(v.x, v.y, H.x, L.x);
    split2(v.z, v.w, H.y, L.y);
    ((uint2*)hi)[i] = H;
    ((uint2*)lo)[i] = L;
}

// =================================================================================
// Tensor-core GEMM (verified R8 core): C = A @ W^T, bf16x3.
// Epilogue dispatch: OUT_Q (scale 0.125 -> Qhi/Qlo), OUT_K (-> Khi/Klo),
// OUT_V (-> transposed Vthi/Vtlo), OUT_EXT (+bias -> fp32 out).
// =================================================================================
#define GBM 128
#define GBN 128
#define GKC 32
#define GST 40

__global__ void __launch_bounds__(256) gemm_mma_kernel(
    const float* __restrict__ bias, int out_sel, float* ext_out)
{
    __shared__ __nv_bfloat16 sAhi[GBM * GST];
    __shared__ __nv_bfloat16 sAlo[GBM * GST];
    __shared__ __nv_bfloat16 sBhi[GBN * GST];
    __shared__ __nv_bfloat16 sBlo[GBN * GST];

    const int tid  = threadIdx.x;
    const int lane = tid & 31;
    const int wid  = tid >> 5;
    const int wm0  = (wid & 3) * 32;
    const int wn0  = (wid >> 2) * 64;
    const int m0   = blockIdx.y * GBM;
    const int n0   = blockIdx.x * GBN;

    const int a_r  = lane & 15;
    const int a_c8 = (lane >> 4) << 3;
    const int b_r  = (lane & 7) + (((lane >> 4) & 1) << 3);
    const int b_c8 = ((lane >> 3) & 1) << 3;

    float acc[2][8][4];
    #pragma unroll
    for (int mi = 0; mi < 2; mi++)
        #pragma unroll
        for (int ni = 0; ni < 8; ni++)
            #pragma unroll
            for (int r = 0; r < 4; r++) acc[mi][ni][r] = 0.f;

    for (int kb = 0; kb < EMBED_DIM; kb += GKC) {
        __syncthreads();
        #pragma unroll
        for (int i = 0; i < 2; i++) {
            int f  = tid + (i << 8);
            int r  = f >> 2;
            int ck = (f & 3) * 8;
            size_t ga = (size_t)(m0 + r) * EMBED_DIM + kb + ck;
            size_t gb = (size_t)(n0 + r) * EMBED_DIM + kb + ck;
            uint32_t so = (uint32_t)(r * GST + ck);
            *(uint4*)&sAhi[so] = *(const uint4*)&g_Ahi[ga];
            *(uint4*)&sAlo[so] = *(const uint4*)&g_Alo[ga];
            *(uint4*)&sBhi[so] = *(const uint4*)&g_Whi[gb];
            *(uint4*)&sBlo[so] = *(const uint4*)&g_Wlo[gb];
        }
        __syncthreads();

        #pragma unroll
        for (int kk = 0; kk < GKC; kk += 16) {
            uint32_t ah[2][4], al[2][4], bb[8][2];
            #pragma unroll
            for (int mi = 0; mi < 2; mi++) {
                uint32_t ad = smem_u32(&sAhi[(wm0 + mi * 16 + a_r) * GST + kk + a_c8]);
                ldm_x4(ah[mi][0], ah[mi][1], ah[mi][2], ah[mi][3], ad);
                ad = smem_u32(&sAlo[(wm0 + mi * 16 + a_r) * GST + kk + a_c8]);
                ldm_x4(al[mi][0], al[mi][1], al[mi][2], al[mi][3], ad);
            }
            #pragma unroll
            for (int np = 0; np < 4; np++) {
                uint32_t ad = smem_u32(&sBhi[(wn0 + np * 16 + b_r) * GST + kk + b_c8]);
                ldm_x4(bb[2 * np][0], bb[2 * np][1], bb[2 * np + 1][0], bb[2 * np + 1][1], ad);
            }
            #pragma unroll
            for (int mi = 0; mi < 2; mi++)
                #pragma unroll
                for (int ni = 0; ni < 8; ni++) mma16816(acc[mi][ni], ah[mi], bb[ni]);
            #pragma unroll
            for (int mi = 0; mi < 2; mi++)
                #pragma unroll
                for (int ni = 0; ni < 8; ni++) mma16816(acc[mi][ni], al[mi], bb[ni]);
            #pragma unroll
            for (int np = 0; np < 4; np++) {
                uint32_t ad = smem_u32(&sBlo[(wn0 + np * 16 + b_r) * GST + kk + b_c8]);
                ldm_x4(bb[2 * np][0], bb[2 * np][1], bb[2 * np + 1][0], bb[2 * np + 1][1], ad);
            }
            #pragma unroll
            for (int mi = 0; mi < 2; mi++)
                #pragma unroll
                for (int ni = 0; ni < 8; ni++) mma16816(acc[mi][ni], ah[mi], bb[ni]);
        }
    }

    const int er = lane >> 2;
    const int ec = (lane & 3) * 2;
    #pragma unroll
    for (int mi = 0; mi < 2; mi++) {
        #pragma unroll
        for (int ni = 0; ni < 8; ni++) {
            int row = m0 + wm0 + mi * 16 + er;
            int col = n0 + wn0 + ni * 8 + ec;
            float v00 = acc[mi][ni][0], v01 = acc[mi][ni][1];   // (row,   col/col+1)
            float v10 = acc[mi][ni][2], v11 = acc[mi][ni][3];   // (row+8, col/col+1)
            if (out_sel == OUT_EXT) {
                float b0 = bias ? bias[col] : 0.f, b1 = bias ? bias[col + 1] : 0.f;
                *(float2*)&ext_out[(size_t)row * EMBED_DIM + col] = make_float2(v00 + b0, v01 + b1);
                *(float2*)&ext_out[(size_t)(row + 8) * EMBED_DIM + col] = make_float2(v10 + b0, v11 + b1);
            } else if (out_sel == OUT_V) {
                // transposed: g_Vt[bh][d][token]
                int bb_ = row >> 11, tok = row & 2047;
                int hh  = col >> 6,  dd  = col & 63;
                size_t base = ((size_t)(bb_ * 16 + hh) * 64 + dd) * SEQ_LEN + tok;
                uint32_t h0, l0, h1, l1;
                split2(v00, v10, h0, l0);   // tokens tok, tok+8 at d=dd -> NOT adjacent; store scalars
                split2(v01, v11, h1, l1);
                g_Vthi[base]               = __ushort_as_bfloat16((unsigned short)(h0 & 0xffff));
                g_Vthi[base + 8]           = __ushort_as_bfloat16((unsigned short)(h0 >> 16));
                g_Vtlo[base]               = __ushort_as_bfloat16((unsigned short)(l0 & 0xffff));
                g_Vtlo[base + 8]           = __ushort_as_bfloat16((unsigned short)(l0 >> 16));
                g_Vthi[base + SEQ_LEN]     = __ushort_as_bfloat16((unsigned short)(h1 & 0xffff));
                g_Vthi[base + SEQ_LEN + 8] = __ushort_as_bfloat16((unsigned short)(h1 >> 16));
                g_Vtlo[base + SEQ_LEN]     = __ushort_as_bfloat16((unsigned short)(l1 & 0xffff));
                g_Vtlo[base + SEQ_LEN + 8] = __ushort_as_bfloat16((unsigned short)(l1 >> 16));
            } else {
                __nv_bfloat16* hi = (out_sel == OUT_Q) ? g_Qhi : g_Khi;
                __nv_bfloat16* lo = (out_sel == OUT_Q) ? g_Qlo : g_Klo;
                float sc = (out_sel == OUT_Q) ? 0.125f : 1.f;
                uint32_t h, l;
                split2(v00 * sc, v01 * sc, h, l);
                *(uint32_t*)&hi[(size_t)row * EMBED_DIM + col] = h;
                *(uint32_t*)&lo[(size_t)row * EMBED_DIM + col] = l;
                split2(v10 * sc, v11 * sc, h, l);
                *(uint32_t*)&hi[(size_t)(row + 8) * EMBED_DIM + col] = h;
                *(uint32_t*)&lo[(size_t)(row + 8) * EMBED_DIM + col] = l;
            }
        }
    }
}

// =================================================================================
// Tensor-core flash attention. CTA = (b,h, 128 q-rows); 8 warps x 16 rows.
// 32-key tiles; warp covers ALL keys of its rows -> register-only FA2 softmax.
// S: Q(frags in regs, hi/lo) x K(smem, hi/lo), 3 products.
// PV: P(S-frags repacked, hi/lo) x Vt(smem, hi/lo), 3 products (drop lo*lo).
// Output written as bf16 hi/lo directly into g_Ahi/g_Alo for the final GEMM.
// =================================================================================
#define QT 128
#define KT 32
#define KST 72      // sK row stride (bf16): 64 d + 8 pad; 144B = 9*16 -> ldm conflict-free
#define VST 40      // sVt row stride: 32 keys + 8 pad; 80B pattern (GEMM-proven)

__global__ void __launch_bounds__(256) attn_kernel(const int* __restrict__ mask)
{
    __shared__ __nv_bfloat16 sKhi[KT * KST];
    __shared__ __nv_bfloat16 sKlo[KT * KST];
    __shared__ __nv_bfloat16 sVhi[64 * VST];
    __shared__ __nv_bfloat16 sVlo[64 * VST];
    __shared__ float mk[KT];

    const int tid  = threadIdx.x;
    const int lane = tid & 31;
    const int wid  = tid >> 5;
    const int wm   = wid * 16;
    const int q0   = blockIdx.x * QT;
    const int b    = blockIdx.y >> 4;
    const int h    = blockIdx.y & 15;

    const int er  = lane >> 2;
    const int ec  = (lane & 3) * 2;
    const int b_r  = (lane & 7) + (((lane >> 4) & 1) << 3);
    const int b_c8 = ((lane >> 3) & 1) << 3;

    // ---- Q fragments direct from gmem (A-frag map: a0(er,c) a1(er+8,c) a2(er,c+8) a3)
    uint32_t qh[4][4], ql[4][4];
    {
        size_t r0 = (size_t)(b * SEQ_LEN + q0 + wm + er) * EMBED_DIM + h * HEAD_DIM;
        size_t r1 = r0 + 8 * EMBED_DIM;
        #pragma unroll
        for (int c = 0; c < 4; c++) {
            int cc = c * 16 + ec;
            qh[c][0] = *(const uint32_t*)&g_Qhi[r0 + cc];
            qh[c][1] = *(const uint32_t*)&g_Qhi[r1 + cc];
            qh[c][2] = *(const uint32_t*)&g_Qhi[r0 + cc + 8];
            qh[c][3] = *(const uint32_t*)&g_Qhi[r1 + cc + 8];
            ql[c][0] = *(const uint32_t*)&g_Qlo[r0 + cc];
            ql[c][1] = *(const uint32_t*)&g_Qlo[r1 + cc];
            ql[c][2] = *(const uint32_t*)&g_Qlo[r0 + cc + 8];
            ql[c][3] = *(const uint32_t*)&g_Qlo[r1 + cc + 8];
        }
    }

    float m0r = -1e30f, m1r = -1e30f, l0 = 0.f, l1 = 0.f;
    float o[8][4];
    #pragma unroll
    for (int ni = 0; ni < 8; ni++)
        #pragma unroll
        for (int r = 0; r < 4; r++) o[ni][r] = 0.f;

    for (int kt = 0; kt < SEQ_LEN; kt += KT) {
        __syncthreads();
        {   // K tile: 32 keys x 64 d ; thread: key=tid>>3, c8=(tid&7)*8
            int key = tid >> 3, c8 = (tid & 7) * 8;
            size_t g = (size_t)(b * SEQ_LEN + kt + key) * EMBED_DIM + h * HEAD_DIM + c8;
            *(uint4*)&sKhi[key * KST + c8] = *(const uint4*)&g_Khi[g];
            *(uint4*)&sKlo[key * KST + c8] = *(const uint4*)&g_Klo[g];
        }
        {   // Vt tile: 64 d x 32 keys ; thread: d=tid>>2, kc=(tid&3)*8
            int d = tid >> 2, kc = (tid & 3) * 8;
            size_t g = ((size_t)(b * 16 + h) * HEAD_DIM + d) * SEQ_LEN + kt + kc;
            *(uint4*)&sVhi[d * VST + kc] = *(const uint4*)&g_Vthi[g];
            *(uint4*)&sVlo[d * VST + kc] = *(const uint4*)&g_Vtlo[g];
        }
        if (tid < KT)
            mk[tid] = (mask[b * SEQ_LEN + kt + tid] == 0) ? -1e20f : 0.f;
        __syncthreads();

        // ---- S = Q K^T (3 products), warp: 16 rows x 32 keys = 4 n-frags
        float s[4][4];
        #pragma unroll
        for (int j = 0; j < 4; j++)
            #pragma unroll
            for (int r = 0; r < 4; r++) s[j][r] = 0.f;
        #pragma unroll
        for (int c = 0; c < 4; c++) {
            uint32_t bb[4][2];
            #pragma unroll
            for (int np = 0; np < 2; np++) {
                uint32_t ad = smem_u32(&sKhi[(np * 16 + b_r) * KST + c * 16 + b_c8]);
                ldm_x4(bb[2*np][0], bb[2*np][1], bb[2*np+1][0], bb[2*np+1][1], ad);
            }
            #pragma unroll
            for (int j = 0; j < 4; j++) mma16816(s[j], qh[c], bb[j]);
            #pragma unroll
            for (int j = 0; j < 4; j++) mma16816(s[j], ql[c], bb[j]);
            #pragma unroll
            for (int np = 0; np < 2; np++) {
                uint32_t ad = smem_u32(&sKlo[(np * 16 + b_r) * KST + c * 16 + b_c8]);
                ldm_x4(bb[2*np][0], bb[2*np][1], bb[2*np+1][0], bb[2*np+1][1], ad);
            }
            #pragma unroll
            for (int j = 0; j < 4; j++) mma16816(s[j], qh[c], bb[j]);
        }

        // ---- mask + register FA2 softmax (rows er / er+8; 4-lane row groups)
        #pragma unroll
        for (int j = 0; j < 4; j++) {
            float a0 = mk[j * 8 + ec], a1 = mk[j * 8 + ec + 1];
            s[j][0] += a0; s[j][1] += a1; s[j][2] += a0; s[j][3] += a1;
        }
        float r0 = fmaxf(fmaxf(s[0][0], s[0][1]), fmaxf(s[1][0], s[1][1]));
        r0 = fmaxf(r0, fmaxf(fmaxf(s[2][0], s[2][1]), fmaxf(s[3][0], s[3][1])));
        float r1 = fmaxf(fmaxf(s[0][2], s[0][3]), fmaxf(s[1][2], s[1][3]));
        r1 = fmaxf(r1, fmaxf(fmaxf(s[2][2], s[2][3]), fmaxf(s[3][2], s[3][3])));
        r0 = fmaxf(r0, __shfl_xor_sync(0xffffffffu, r0, 1));
        r0 = fmaxf(r0, __shfl_xor_sync(0xffffffffu, r0, 2));
        r1 = fmaxf(r1, __shfl_xor_sync(0xffffffffu, r1, 1));
        r1 = fmaxf(r1, __shfl_xor_sync(0xffffffffu, r1, 2));
        float mn0 = fmaxf(m0r, r0), mn1 = fmaxf(m1r, r1);
        float al0 = __expf(m0r - mn0), al1 = __expf(m1r - mn1);
        m0r = mn0; m1r = mn1;

        float p[4][4], sum0 = 0.f, sum1 = 0.f;
        #pragma unroll
        for (int j = 0; j < 4; j++) {
            p[j][0] = __expf(s[j][0] - mn0); p[j][1] = __expf(s[j][1] - mn0);
            p[j][2] = __expf(s[j][2] - mn1); p[j][3] = __expf(s[j][3] - mn1);
            sum0 += p[j][0] + p[j][1];
            sum1 += p[j][2] + p[j][3];
        }
        sum0 += __shfl_xor_sync(0xffffffffu, sum0, 1);
        sum0 += __shfl_xor_sync(0xffffffffu, sum0, 2);
        sum1 += __shfl_xor_sync(0xffffffffu, sum1, 1);
        sum1 += __shfl_xor_sync(0xffffffffu, sum1, 2);
        l0 = l0 * al0 + sum0;
        l1 = l1 * al1 + sum1;
        #pragma unroll
        for (int ni = 0; ni < 8; ni++) {
            o[ni][0] *= al0; o[ni][1] *= al0; o[ni][2] *= al1; o[ni][3] *= al1;
        }

        // ---- P -> A-frags (identity layout map), split hi/lo
        uint32_t ph[2][4], pl[2][4];
        #pragma unroll
        for (int c = 0; c < 2; c++) {
            int j0 = 2 * c, j1 = 2 * c + 1;
            split2(p[j0][0], p[j0][1], ph[c][0], pl[c][0]);
            split2(p[j0][2], p[j0][3], ph[c][1], pl[c][1]);
            split2(p[j1][0], p[j1][1], ph[c][2], pl[c][2]);
            split2(p[j1][2], p[j1][3], ph[c][3], pl[c][3]);
        }

        // ---- O += P V (3 products)
        #pragma unroll
        for (int c = 0; c < 2; c++) {
            uint32_t vb[8][2];
            #pragma unroll
            for (int np = 0; np < 4; np++) {
                uint32_t ad = smem_u32(&sVhi[(np * 16 + b_r) * VST + c * 16 + b_c8]);
                ldm_x4(vb[2*np][0], vb[2*np][1], vb[2*np+1][0], vb[2*np+1][1], ad);
            }
            #pragma unroll
            for (int ni = 0; ni < 8; ni++) mma16816(o[ni], ph[c], vb[ni]);
            #pragma unroll
            for (int ni = 0; ni < 8; ni++) mma16816(o[ni], pl[c], vb[ni]);
            #pragma unroll
            for (int np = 0; np < 4; np++) {
                uint32_t ad = smem_u32(&sVlo[(np * 16 + b_r) * VST + c * 16 + b_c8]);
                ldm_x4(vb[2*np][0], vb[2*np][1], vb[2*np+1][0], vb[2*np+1][1], ad);
            }
            #pragma unroll
            for (int ni = 0; ni < 8; ni++) mma16816(o[ni], ph[c], vb[ni]);
        }
    }

    // ---- epilogue: normalize, split, write AO hi/lo into the GEMM-A buffers
    {
        float i0 = 1.f / l0, i1 = 1.f / l1;
        size_t r0o = (size_t)(b * SEQ_LEN + q0 + wm + er) * EMBED_DIM + h * HEAD_DIM;
        size_t r1o = r0o + 8 * EMBED_DIM;
        #pragma unroll
        for (int ni = 0; ni < 8; ni++) {
            int d = ni * 8 + ec;
            uint32_t hh, ll;
            split2(o[ni][0] * i0, o[ni][1] * i0, hh, ll);
            *(uint32_t*)&g_Ahi[r0o + d] = hh;
            *(uint32_t*)&g_Alo[r0o + d] = ll;
            split2(o[ni][2] * i1, o[ni][3] * i1, hh, ll);
            *(uint32_t*)&g_Ahi[r1o + d] = hh;
            *(uint32_t*)&g_Alo[r1o + d] = ll;
        }
    }
}

// =================================================================================
// kernel_launch: PURE kernel launches — no runtime API calls.
// =================================================================================
extern "C" void kernel_launch(void* const* d_in, const int* in_sizes, int n_in,
                              void* d_out, int out_size)
{
    const float* values = (const float*)d_in[0];
    const float* keys   = (const float*)d_in[1];
    const float* query  = (const float*)d_in[2];
    const int*   mask   = (const int*)  d_in[3];
    const float* W_q    = (const float*)d_in[4];
    const float* W_k    = (const float*)d_in[5];
    const float* W_v    = (const float*)d_in[6];
    const float* W_o    = (const float*)d_in[7];
    const float* b_o    = (const float*)d_in[8];
    float* out = (float*)d_out;

    const int nA4 = NTOK * EMBED_DIM / 4;
    const int nW4 = EMBED_DIM * EMBED_DIM / 4;
    dim3 tgrid(EMBED_DIM / GBN, NTOK / GBM);      // (8, 32)

    split_kernel<<<nA4 / 256, 256>>>(query, 0, nA4);
    split_kernel<<<nW4 / 256, 256>>>(W_q,   1, nW4);
    gemm_mma_kernel<<<tgrid, 256>>>(nullptr, OUT_Q, nullptr);

    split_kernel<<<nA4 / 256, 256>>>(keys,  0, nA4);
    split_kernel<<<nW4 / 256, 256>>>(W_k,   1, nW4);
    gemm_mma_kernel<<<tgrid, 256>>>(nullptr, OUT_K, nullptr);

    split_kernel<<<nA4 / 256, 256>>>(values, 0, nA4);
    split_kernel<<<nW4 / 256, 256>>>(W_v,    1, nW4);
    gemm_mma_kernel<<<tgrid, 256>>>(nullptr, OUT_V, nullptr);

    dim3 agrid(SEQ_LEN / QT, 2 * 16);             // (16, 32) = 512 CTAs
    attn_kernel<<<agrid, 256>>>(mask);            // writes g_Ahi/g_Alo

    split_kernel<<<nW4 / 256, 256>>>(W_o, 1, nW4);
    gemm_mma_kernel<<<tgrid, 256>>>(b_o, OUT_EXT, out);
}

// round 11
// speedup vs baseline: 2.2574x; 1.5524x over previous
#include <cuda_runtime.h>
#include <cuda_bf16.h>
#include <cstdint>

// Problem constants: N=2, L=2048, EMBED=1024, HEADS=16, Dh=64
#define SEQ_LEN   2048
#define EMBED_DIM 1024
#define NTOK      4096
#define HEAD_DIM  64

// ---------------- warp-MMA helpers (verified R8/R9) ----------------
__device__ __forceinline__ uint32_t smem_u32(const void* p) {
    uint32_t a;
    asm("{ .reg .u64 t; cvta.to.shared.u64 t, %1; cvt.u32.u64 %0, t; }"
        : "=r"(a) : "l"(p));
    return a;
}
__device__ __forceinline__ void ldm_x4(uint32_t& r0, uint32_t& r1,
                                       uint32_t& r2, uint32_t& r3, uint32_t addr) {
    asm volatile("ldmatrix.sync.aligned.m8n8.x4.shared.b16 {%0,%1,%2,%3}, [%4];"
                 : "=r"(r0), "=r"(r1), "=r"(r2), "=r"(r3) : "r"(addr));
}
__device__ __forceinline__ void mma16816(float* c, const uint32_t* a, const uint32_t* b) {
    asm volatile(
        "mma.sync.aligned.m16n8k16.row.col.f32.bf16.bf16.f32 "
        "{%0,%1,%2,%3}, {%4,%5,%6,%7}, {%8,%9}, {%0,%1,%2,%3};"
        : "+f"(c[0]), "+f"(c[1]), "+f"(c[2]), "+f"(c[3])
        : "r"(a[0]), "r"(a[1]), "r"(a[2]), "r"(a[3]), "r"(b[0]), "r"(b[1]));
}
__device__ __forceinline__ void split2(float a, float b, uint32_t& h, uint32_t& l) {
    __nv_bfloat16 ha = __float2bfloat16(a), hb = __float2bfloat16(b);
    __nv_bfloat16 la = __float2bfloat16(a - __bfloat162float(ha));
    __nv_bfloat16 lb = __float2bfloat16(b - __bfloat162float(hb));
    h = (uint32_t)__bfloat16_as_ushort(ha) | ((uint32_t)__bfloat16_as_ushort(hb) << 16);
    l = (uint32_t)__bfloat16_as_ushort(la) | ((uint32_t)__bfloat16_as_ushort(lb) << 16);
}

// ---------------- scratch (device globals: allocation-guard safe) ----------------
__device__ __nv_bfloat16 g_Ahi [NTOK * EMBED_DIM];
__device__ __nv_bfloat16 g_Alo [NTOK * EMBED_DIM];
__device__ __nv_bfloat16 g_Whi [EMBED_DIM * EMBED_DIM];
__device__ __nv_bfloat16 g_Wlo [EMBED_DIM * EMBED_DIM];
__device__ __nv_bfloat16 g_Qhi [NTOK * EMBED_DIM];   // pre-scaled by 0.125
__device__ __nv_bfloat16 g_Qlo [NTOK * EMBED_DIM];
__device__ __nv_bfloat16 g_Khi [NTOK * EMBED_DIM];
__device__ __nv_bfloat16 g_Klo [NTOK * EMBED_DIM];
__device__ __nv_bfloat16 g_Vthi[NTOK * EMBED_DIM];   // [bh][d][token]
__device__ __nv_bfloat16 g_Vtlo[NTOK * EMBED_DIM];

#define OUT_Q   0
#define OUT_K   1
#define OUT_V   2
#define OUT_EXT 4

// =================================================================================
// split_kernel: fp32 -> (hi bf16, lo bf16).
// =================================================================================
__global__ void __launch_bounds__(256) split_kernel(
    const float* __restrict__ x, int dst, int n4)
{
    __nv_bfloat16* __restrict__ hi = dst ? g_Whi : g_Ahi;
    __nv_bfloat16* __restrict__ lo = dst ? g_Wlo : g_Alo;
    int i = blockIdx.x * blockDim.x + threadIdx.x;
    if (i >= n4) return;
    float4 v = ((const float4*)x)[i];
    uint2 H, L;
    split2(v.x, v.y, H.x, L.x);
    split2(v.z, v.w, H.y, L.y);
    ((uint2*)hi)[i] = H;
    ((uint2*)lo)[i] = L;
}

// =================================================================================
// Tensor-core GEMM (verified core) + register-prefetch pipeline on the k-loop.
// =================================================================================
#define GBM 128
#define GBN 128
#define GKC 32
#define GST 40

__global__ void __launch_bounds__(256) gemm_mma_kernel(
    const float* __restrict__ bias, int out_sel, float* ext_out)
{
    __shared__ __nv_bfloat16 sAhi[GBM * GST];
    __shared__ __nv_bfloat16 sAlo[GBM * GST];
    __shared__ __nv_bfloat16 sBhi[GBN * GST];
    __shared__ __nv_bfloat16 sBlo[GBN * GST];

    const int tid  = threadIdx.x;
    const int lane = tid & 31;
    const int wid  = tid >> 5;
    const int wm0  = (wid & 3) * 32;
    const int wn0  = (wid >> 2) * 64;
    const int m0   = blockIdx.y * GBM;
    const int n0   = blockIdx.x * GBN;

    const int a_r  = lane & 15;
    const int a_c8 = (lane >> 4) << 3;
    const int b_r  = (lane & 7) + (((lane >> 4) & 1) << 3);
    const int b_c8 = ((lane >> 3) & 1) << 3;

    float acc[2][8][4];
    #pragma unroll
    for (int mi = 0; mi < 2; mi++)
        #pragma unroll
        for (int ni = 0; ni < 8; ni++)
            #pragma unroll
            for (int r = 0; r < 4; r++) acc[mi][ni][r] = 0.f;

    // per-thread staging indices (fixed)
    int sr[2], sck[2];
    #pragma unroll
    for (int i = 0; i < 2; i++) {
        int f = tid + (i << 8);
        sr[i]  = f >> 2;
        sck[i] = (f & 3) * 8;
    }

    // prefetch registers: tile kb currently staged in regs
    uint4 rAh[2], rAl[2], rBh[2], rBl[2];
    #pragma unroll
    for (int i = 0; i < 2; i++) {
        size_t ga = (size_t)(m0 + sr[i]) * EMBED_DIM + sck[i];
        size_t gb = (size_t)(n0 + sr[i]) * EMBED_DIM + sck[i];
        rAh[i] = *(const uint4*)&g_Ahi[ga];
        rAl[i] = *(const uint4*)&g_Alo[ga];
        rBh[i] = *(const uint4*)&g_Whi[gb];
        rBl[i] = *(const uint4*)&g_Wlo[gb];
    }

    for (int kb = 0; kb < EMBED_DIM; kb += GKC) {
        __syncthreads();                          // readers of previous tile done
        #pragma unroll
        for (int i = 0; i < 2; i++) {
            uint32_t so = (uint32_t)(sr[i] * GST + sck[i]);
            *(uint4*)&sAhi[so] = rAh[i];
            *(uint4*)&sAlo[so] = rAl[i];
            *(uint4*)&sBhi[so] = rBh[i];
            *(uint4*)&sBlo[so] = rBl[i];
        }
        __syncthreads();                          // tile visible

        if (kb + GKC < EMBED_DIM) {               // LDG next tile; overlaps compute
            #pragma unroll
            for (int i = 0; i < 2; i++) {
                size_t ga = (size_t)(m0 + sr[i]) * EMBED_DIM + kb + GKC + sck[i];
                size_t gb = (size_t)(n0 + sr[i]) * EMBED_DIM + kb + GKC + sck[i];
                rAh[i] = *(const uint4*)&g_Ahi[ga];
                rAl[i] = *(const uint4*)&g_Alo[ga];
                rBh[i] = *(const uint4*)&g_Whi[gb];
                rBl[i] = *(const uint4*)&g_Wlo[gb];
            }
        }

        #pragma unroll
        for (int kk = 0; kk < GKC; kk += 16) {
            uint32_t ah[2][4], al[2][4], bb[8][2];
            #pragma unroll
            for (int mi = 0; mi < 2; mi++) {
                uint32_t ad = smem_u32(&sAhi[(wm0 + mi * 16 + a_r) * GST + kk + a_c8]);
                ldm_x4(ah[mi][0], ah[mi][1], ah[mi][2], ah[mi][3], ad);
                ad = smem_u32(&sAlo[(wm0 + mi * 16 + a_r) * GST + kk + a_c8]);
                ldm_x4(al[mi][0], al[mi][1], al[mi][2], al[mi][3], ad);
            }
            #pragma unroll
            for (int np = 0; np < 4; np++) {
                uint32_t ad = smem_u32(&sBhi[(wn0 + np * 16 + b_r) * GST + kk + b_c8]);
                ldm_x4(bb[2 * np][0], bb[2 * np][1], bb[2 * np + 1][0], bb[2 * np + 1][1], ad);
            }
            #pragma unroll
            for (int mi = 0; mi < 2; mi++)
                #pragma unroll
                for (int ni = 0; ni < 8; ni++) mma16816(acc[mi][ni], ah[mi], bb[ni]);
            #pragma unroll
            for (int mi = 0; mi < 2; mi++)
                #pragma unroll
                for (int ni = 0; ni < 8; ni++) mma16816(acc[mi][ni], al[mi], bb[ni]);
            #pragma unroll
            for (int np = 0; np < 4; np++) {
                uint32_t ad = smem_u32(&sBlo[(wn0 + np * 16 + b_r) * GST + kk + b_c8]);
                ldm_x4(bb[2 * np][0], bb[2 * np][1], bb[2 * np + 1][0], bb[2 * np + 1][1], ad);
            }
            #pragma unroll
            for (int mi = 0; mi < 2; mi++)
                #pragma unroll
                for (int ni = 0; ni < 8; ni++) mma16816(acc[mi][ni], ah[mi], bb[ni]);
        }
    }

    const int er = lane >> 2;
    const int ec = (lane & 3) * 2;
    #pragma unroll
    for (int mi = 0; mi < 2; mi++) {
        #pragma unroll
        for (int ni = 0; ni < 8; ni++) {
            int row = m0 + wm0 + mi * 16 + er;
            int col = n0 + wn0 + ni * 8 + ec;
            float v00 = acc[mi][ni][0], v01 = acc[mi][ni][1];
            float v10 = acc[mi][ni][2], v11 = acc[mi][ni][3];
            if (out_sel == OUT_EXT) {
                float b0 = bias ? bias[col] : 0.f, b1 = bias ? bias[col + 1] : 0.f;
                *(float2*)&ext_out[(size_t)row * EMBED_DIM + col] = make_float2(v00 + b0, v01 + b1);
                *(float2*)&ext_out[(size_t)(row + 8) * EMBED_DIM + col] = make_float2(v10 + b0, v11 + b1);
            } else if (out_sel == OUT_V) {
                int bb_ = row >> 11, tok = row & 2047;
                int hh  = col >> 6,  dd  = col & 63;
                size_t base = ((size_t)(bb_ * 16 + hh) * 64 + dd) * SEQ_LEN + tok;
                uint32_t h0, l0, h1, l1;
                split2(v00, v10, h0, l0);
                split2(v01, v11, h1, l1);
                g_Vthi[base]               = __ushort_as_bfloat16((unsigned short)(h0 & 0xffff));
                g_Vthi[base + 8]           = __ushort_as_bfloat16((unsigned short)(h0 >> 16));
                g_Vtlo[base]               = __ushort_as_bfloat16((unsigned short)(l0 & 0xffff));
                g_Vtlo[base + 8]           = __ushort_as_bfloat16((unsigned short)(l0 >> 16));
                g_Vthi[base + SEQ_LEN]     = __ushort_as_bfloat16((unsigned short)(h1 & 0xffff));
                g_Vthi[base + SEQ_LEN + 8] = __ushort_as_bfloat16((unsigned short)(h1 >> 16));
                g_Vtlo[base + SEQ_LEN]     = __ushort_as_bfloat16((unsigned short)(l1 & 0xffff));
                g_Vtlo[base + SEQ_LEN + 8] = __ushort_as_bfloat16((unsigned short)(l1 >> 16));
            } else {
                __nv_bfloat16* hi = (out_sel == OUT_Q) ? g_Qhi : g_Khi;
                __nv_bfloat16* lo = (out_sel == OUT_Q) ? g_Qlo : g_Klo;
                float sc = (out_sel == OUT_Q) ? 0.125f : 1.f;
                uint32_t h, l;
                split2(v00 * sc, v01 * sc, h, l);
                *(uint32_t*)&hi[(size_t)row * EMBED_DIM + col] = h;
                *(uint32_t*)&lo[(size_t)row * EMBED_DIM + col] = l;
                split2(v10 * sc, v11 * sc, h, l);
                *(uint32_t*)&hi[(size_t)(row + 8) * EMBED_DIM + col] = h;
                *(uint32_t*)&lo[(size_t)(row + 8) * EMBED_DIM + col] = l;
            }
        }
    }
}

// =================================================================================
// Tensor-core flash attention (verified R9 math) + 2-stage smem double-buffer:
// LDG(t+1) -> compute(t) -> STS(t+1 into other buffer) -> ONE syncthreads.
// smem: 2 x 19.3KB + mask = 39.4KB (<48KB; 2 CTAs/SM by smem).
// =================================================================================
#define QT 128
#define KT 32
#define KST 72
#define VST 40
#define NT (SEQ_LEN / KT)     // 64 tiles

__global__ void __launch_bounds__(256) attn_kernel(const int* __restrict__ mask)
{
    __shared__ __nv_bfloat16 sKhi[2][KT * KST];
    __shared__ __nv_bfloat16 sKlo[2][KT * KST];
    __shared__ __nv_bfloat16 sVhi[2][64 * VST];
    __shared__ __nv_bfloat16 sVlo[2][64 * VST];
    __shared__ float mk[2][KT];

    const int tid  = threadIdx.x;
    const int lane = tid & 31;
    const int wid  = tid >> 5;
    const int wm   = wid * 16;
    const int q0   = blockIdx.x * QT;
    const int b    = blockIdx.y >> 4;
    const int h    = blockIdx.y & 15;

    const int er   = lane >> 2;
    const int ec   = (lane & 3) * 2;
    const int b_r  = (lane & 7) + (((lane >> 4) & 1) << 3);
    const int b_c8 = ((lane >> 3) & 1) << 3;

    // fixed per-thread staging indices
    const int k_key = tid >> 3, k_c8 = (tid & 7) * 8;
    const int v_d   = tid >> 2, v_kc = (tid & 3) * 8;
    const size_t kbase = (size_t)(b * SEQ_LEN + k_key) * EMBED_DIM + h * HEAD_DIM + k_c8;
    const size_t vbase = ((size_t)(b * 16 + h) * HEAD_DIM + v_d) * SEQ_LEN + v_kc;

    // ---- Q fragments direct from gmem
    uint32_t qh[4][4], ql[4][4];
    {
        size_t r0 = (size_t)(b * SEQ_LEN + q0 + wm + er) * EMBED_DIM + h * HEAD_DIM;
        size_t r1 = r0 + 8 * EMBED_DIM;
        #pragma unroll
        for (int c = 0; c < 4; c++) {
            int cc = c * 16 + ec;
            qh[c][0] = *(const uint32_t*)&g_Qhi[r0 + cc];
            qh[c][1] = *(const uint32_t*)&g_Qhi[r1 + cc];
            qh[c][2] = *(const uint32_t*)&g_Qhi[r0 + cc + 8];
            qh[c][3] = *(const uint32_t*)&g_Qhi[r1 + cc + 8];
            ql[c][0] = *(const uint32_t*)&g_Qlo[r0 + cc];
            ql[c][1] = *(const uint32_t*)&g_Qlo[r1 + cc];
            ql[c][2] = *(const uint32_t*)&g_Qlo[r0 + cc + 8];
            ql[c][3] = *(const uint32_t*)&g_Qlo[r1 + cc + 8];
        }
    }

    float m0r = -1e30f, m1r = -1e30f, l0 = 0.f, l1 = 0.f;
    float o[8][4];
    #pragma unroll
    for (int ni = 0; ni < 8; ni++)
        #pragma unroll
        for (int r = 0; r < 4; r++) o[ni][r] = 0.f;

    // ---- preload tile 0 into buffer 0
    {
        uint4 kh = *(const uint4*)&g_Khi[kbase];
        uint4 kl = *(const uint4*)&g_Klo[kbase];
        uint4 vh = *(const uint4*)&g_Vthi[vbase];
        uint4 vl = *(const uint4*)&g_Vtlo[vbase];
        *(uint4*)&sKhi[0][k_key * KST + k_c8] = kh;
        *(uint4*)&sKlo[0][k_key * KST + k_c8] = kl;
        *(uint4*)&sVhi[0][v_d * VST + v_kc]   = vh;
        *(uint4*)&sVlo[0][v_d * VST + v_kc]   = vl;
        if (tid < KT)
            mk[0][tid] = (mask[b * SEQ_LEN + tid] == 0) ? -1e20f : 0.f;
    }
    __syncthreads();

    for (int ti = 0; ti < NT; ti++) {
        const int cur = ti & 1;
        const bool nx = (ti + 1) < NT;

        // ---- LDG next tile into registers (latency overlapped by compute below)
        uint4 nkh, nkl, nvh, nvl; int nmv = 1;
        if (nx) {
            size_t kg = kbase + (size_t)(ti + 1) * KT * EMBED_DIM;
            size_t vg = vbase + (size_t)(ti + 1) * KT;
            nkh = *(const uint4*)&g_Khi[kg];
            nkl = *(const uint4*)&g_Klo[kg];
            nvh = *(const uint4*)&g_Vthi[vg];
            nvl = *(const uint4*)&g_Vtlo[vg];
            if (tid < KT) nmv = mask[b * SEQ_LEN + (ti + 1) * KT + tid];
        }

        // ---- S = Q K^T (3 products)
        float s[4][4];
        #pragma unroll
        for (int j = 0; j < 4; j++)
            #pragma unroll
            for (int r = 0; r < 4; r++) s[j][r] = 0.f;
        #pragma unroll
        for (int c = 0; c < 4; c++) {
            uint32_t bb[4][2];
            #pragma unroll
            for (int np = 0; np < 2; np++) {
                uint32_t ad = smem_u32(&sKhi[cur][(np * 16 + b_r) * KST + c * 16 + b_c8]);
                ldm_x4(bb[2*np][0], bb[2*np][1], bb[2*np+1][0], bb[2*np+1][1], ad);
            }
            #pragma unroll
            for (int j = 0; j < 4; j++) mma16816(s[j], qh[c], bb[j]);
            #pragma unroll
            for (int j = 0; j < 4; j++) mma16816(s[j], ql[c], bb[j]);
            #pragma unroll
            for (int np = 0; np < 2; np++) {
                uint32_t ad = smem_u32(&sKlo[cur][(np * 16 + b_r) * KST + c * 16 + b_c8]);
                ldm_x4(bb[2*np][0], bb[2*np][1], bb[2*np+1][0], bb[2*np+1][1], ad);
            }
            #pragma unroll
            for (int j = 0; j < 4; j++) mma16816(s[j], qh[c], bb[j]);
        }

        // ---- mask + register FA2 softmax
        #pragma unroll
        for (int j = 0; j < 4; j++) {
            float a0 = mk[cur][j * 8 + ec], a1 = mk[cur][j * 8 + ec + 1];
            s[j][0] += a0; s[j][1] += a1; s[j][2] += a0; s[j][3] += a1;
        }
        float r0 = fmaxf(fmaxf(s[0][0], s[0][1]), fmaxf(s[1][0], s[1][1]));
        r0 = fmaxf(r0, fmaxf(fmaxf(s[2][0], s[2][1]), fmaxf(s[3][0], s[3][1])));
        float r1 = fmaxf(fmaxf(s[0][2], s[0][3]), fmaxf(s[1][2], s[1][3]));
        r1 = fmaxf(r1, fmaxf(fmaxf(s[2][2], s[2][3]), fmaxf(s[3][2], s[3][3])));
        r0 = fmaxf(r0, __shfl_xor_sync(0xffffffffu, r0, 1));
        r0 = fmaxf(r0, __shfl_xor_sync(0xffffffffu, r0, 2));
        r1 = fmaxf(r1, __shfl_xor_sync(0xffffffffu, r1, 1));
        r1 = fmaxf(r1, __shfl_xor_sync(0xffffffffu, r1, 2));
        float mn0 = fmaxf(m0r, r0), mn1 = fmaxf(m1r, r1);
        float al0 = __expf(m0r - mn0), al1 = __expf(m1r - mn1);
        m0r = mn0; m1r = mn1;

        float p[4][4], sum0 = 0.f, sum1 = 0.f;
        #pragma unroll
        for (int j = 0; j < 4; j++) {
            p[j][0] = __expf(s[j][0] - mn0); p[j][1] = __expf(s[j][1] - mn0);
            p[j][2] = __expf(s[j][2] - mn1); p[j][3] = __expf(s[j][3] - mn1);
            sum0 += p[j][0] + p[j][1];
            sum1 += p[j][2] + p[j][3];
        }
        sum0 += __shfl_xor_sync(0xffffffffu, sum0, 1);
        sum0 += __shfl_xor_sync(0xffffffffu, sum0, 2);
        sum1 += __shfl_xor_sync(0xffffffffu, sum1, 1);
        sum1 += __shfl_xor_sync(0xffffffffu, sum1, 2);
        l0 = l0 * al0 + sum0;
        l1 = l1 * al1 + sum1;
        #pragma unroll
        for (int ni = 0; ni < 8; ni++) {
            o[ni][0] *= al0; o[ni][1] *= al0; o[ni][2] *= al1; o[ni][3] *= al1;
        }

        // ---- P -> A-frags, split hi/lo
        uint32_t ph[2][4], pl[2][4];
        #pragma unroll
        for (int c = 0; c < 2; c++) {
            int j0 = 2 * c, j1 = 2 * c + 1;
            split2(p[j0][0], p[j0][1], ph[c][0], pl[c][0]);
            split2(p[j0][2], p[j0][3], ph[c][1], pl[c][1]);
            split2(p[j1][0], p[j1][1], ph[c][2], pl[c][2]);
            split2(p[j1][2], p[j1][3], ph[c][3], pl[c][3]);
        }

        // ---- O += P V (3 products)
        #pragma unroll
        for (int c = 0; c < 2; c++) {
            uint32_t vb[8][2];
            #pragma unroll
            for (int np = 0; np < 4; np++) {
                uint32_t ad = smem_u32(&sVhi[cur][(np * 16 + b_r) * VST + c * 16 + b_c8]);
                ldm_x4(vb[2*np][0], vb[2*np][1], vb[2*np+1][0], vb[2*np+1][1], ad);
            }
            #pragma unroll
            for (int ni = 0; ni < 8; ni++) mma16816(o[ni], ph[c], vb[ni]);
            #pragma unroll
            for (int ni = 0; ni < 8; ni++) mma16816(o[ni], pl[c], vb[ni]);
            #pragma unroll
            for (int np = 0; np < 4; np++) {
                uint32_t ad = smem_u32(&sVlo[cur][(np * 16 + b_r) * VST + c * 16 + b_c8]);
                ldm_x4(vb[2*np][0], vb[2*np][1], vb[2*np+1][0], vb[2*np+1][1], ad);
            }
            #pragma unroll
            for (int ni = 0; ni < 8; ni++) mma16816(o[ni], ph[c], vb[ni]);
        }

        // ---- STS next tile into the other buffer; one sync per iteration
        if (nx) {
            int nb = cur ^ 1;
            *(uint4*)&sKhi[nb][k_key * KST + k_c8] = nkh;
            *(uint4*)&sKlo[nb][k_key * KST + k_c8] = nkl;
            *(uint4*)&sVhi[nb][v_d * VST + v_kc]   = nvh;
            *(uint4*)&sVlo[nb][v_d * VST + v_kc]   = nvl;
            if (tid < KT) mk[nb][tid] = (nmv == 0) ? -1e20f : 0.f;
        }
        __syncthreads();
    }

    // ---- epilogue: normalize, split, write AO hi/lo into GEMM-A buffers
    {
        float i0 = 1.f / l0, i1 = 1.f / l1;
        size_t r0o = (size_t)(b * SEQ_LEN + q0 + wm + er) * EMBED_DIM + h * HEAD_DIM;
        size_t r1o = r0o + 8 * EMBED_DIM;
        #pragma unroll
        for (int ni = 0; ni < 8; ni++) {
            int d = ni * 8 + ec;
            uint32_t hh, ll;
            split2(o[ni][0] * i0, o[ni][1] * i0, hh, ll);
            *(uint32_t*)&g_Ahi[r0o + d] = hh;
            *(uint32_t*)&g_Alo[r0o + d] = ll;
            split2(o[ni][2] * i1, o[ni][3] * i1, hh, ll);
            *(uint32_t*)&g_Ahi[r1o + d] = hh;
            *(uint32_t*)&g_Alo[r1o + d] = ll;
        }
    }
}

// =================================================================================
// kernel_launch: PURE kernel launches — no runtime API calls.
// =================================================================================
extern "C" void kernel_launch(void* const* d_in, const int* in_sizes, int n_in,
                              void* d_out, int out_size)
{
    const float* values = (const float*)d_in[0];
    const float* keys   = (const float*)d_in[1];
    const float* query  = (const float*)d_in[2];
    const int*   mask   = (const int*)  d_in[3];
    const float* W_q    = (const float*)d_in[4];
    const float* W_k    = (const float*)d_in[5];
    const float* W_v    = (const float*)d_in[6];
    const float* W_o    = (const float*)d_in[7];
    const float* b_o    = (const float*)d_in[8];
    float* out = (float*)d_out;

    const int nA4 = NTOK * EMBED_DIM / 4;
    const int nW4 = EMBED_DIM * EMBED_DIM / 4;
    dim3 tgrid(EMBED_DIM / GBN, NTOK / GBM);

    split_kernel<<<nA4 / 256, 256>>>(query, 0, nA4);
    split_kernel<<<nW4 / 256, 256>>>(W_q,   1, nW4);
    gemm_mma_kernel<<<tgrid, 256>>>(nullptr, OUT_Q, nullptr);

    split_kernel<<<nA4 / 256, 256>>>(keys,  0, nA4);
    split_kernel<<<nW4 / 256, 256>>>(W_k,   1, nW4);
    gemm_mma_kernel<<<tgrid, 256>>>(nullptr, OUT_K, nullptr);

    split_kernel<<<nA4 / 256, 256>>>(values, 0, nA4);
    split_kernel<<<nW4 / 256, 256>>>(W_v,    1, nW4);
    gemm_mma_kernel<<<tgrid, 256>>>(nullptr, OUT_V, nullptr);

    dim3 agrid(SEQ_LEN / QT, 2 * 16);
    attn_kernel<<<agrid, 256>>>(mask);

    split_kernel<<<nW4 / 256, 256>>>(W_o, 1, nW4);
    gemm_mma_kernel<<<tgrid, 256>>>(b_o, OUT_EXT, out);
}

// round 12
// speedup vs baseline: 2.5678x; 1.1375x over previous
#include <cuda_runtime.h>
#include <cuda_bf16.h>
#include <cstdint>

// Problem constants: N=2, L=2048, EMBED=1024, HEADS=16, Dh=64
#define SEQ_LEN   2048
#define EMBED_DIM 1024
#define NTOK      4096
#define HEAD_DIM  64

// ---------------- warp-MMA helpers (verified R8-R11) ----------------
__device__ __forceinline__ uint32_t smem_u32(const void* p) {
    uint32_t a;
    asm("{ .reg .u64 t; cvta.to.shared.u64 t, %1; cvt.u32.u64 %0, t; }"
        : "=r"(a) : "l"(p));
    return a;
}
__device__ __forceinline__ void ldm_x4(uint32_t& r0, uint32_t& r1,
                                       uint32_t& r2, uint32_t& r3, uint32_t addr) {
    asm volatile("ldmatrix.sync.aligned.m8n8.x4.shared.b16 {%0,%1,%2,%3}, [%4];"
                 : "=r"(r0), "=r"(r1), "=r"(r2), "=r"(r3) : "r"(addr));
}
__device__ __forceinline__ void mma16816(float* c, const uint32_t* a, const uint32_t* b) {
    asm volatile(
        "mma.sync.aligned.m16n8k16.row.col.f32.bf16.bf16.f32 "
        "{%0,%1,%2,%3}, {%4,%5,%6,%7}, {%8,%9}, {%0,%1,%2,%3};"
        : "+f"(c[0]), "+f"(c[1]), "+f"(c[2]), "+f"(c[3])
        : "r"(a[0]), "r"(a[1]), "r"(a[2]), "r"(a[3]), "r"(b[0]), "r"(b[1]));
}
__device__ __forceinline__ void split2(float a, float b, uint32_t& h, uint32_t& l) {
    __nv_bfloat16 ha = __float2bfloat16(a), hb = __float2bfloat16(b);
    __nv_bfloat16 la = __float2bfloat16(a - __bfloat162float(ha));
    __nv_bfloat16 lb = __float2bfloat16(b - __bfloat162float(hb));
    h = (uint32_t)__bfloat16_as_ushort(ha) | ((uint32_t)__bfloat16_as_ushort(hb) << 16);
    l = (uint32_t)__bfloat16_as_ushort(la) | ((uint32_t)__bfloat16_as_ushort(lb) << 16);
}

// cp.async (sm_80 baseline PTX; fine at compute_103)
#define CPA16(sa, ga) \
    asm volatile("cp.async.cg.shared.global [%0], [%1], 16;" :: "r"(sa), "l"(ga))
#define CPA_COMMIT() asm volatile("cp.async.commit_group;" ::: "memory")
#define CPA_WAIT0()  asm volatile("cp.async.wait_group 0;" ::: "memory")

// ---------------- scratch (device globals: allocation-guard safe) ----------------
__device__ __nv_bfloat16 g_Ahi [NTOK * EMBED_DIM];   // attn output -> final GEMM A
__device__ __nv_bfloat16 g_Alo [NTOK * EMBED_DIM];
__device__ __nv_bfloat16 g_Qhi [NTOK * EMBED_DIM];   // pre-scaled by 0.125
__device__ __nv_bfloat16 g_Qlo [NTOK * EMBED_DIM];
__device__ __nv_bfloat16 g_Khi [NTOK * EMBED_DIM];
__device__ __nv_bfloat16 g_Klo [NTOK * EMBED_DIM];
__device__ __nv_bfloat16 g_Vthi[NTOK * EMBED_DIM];   // [bh][d][token]
__device__ __nv_bfloat16 g_Vtlo[NTOK * EMBED_DIM];

#define OUT_Q   0
#define OUT_K   1
#define OUT_V   2
#define OUT_EXT 4

// staged pair: either (hi uint4, lo uint4) [bf16 path] or 8 raw fp32 [fp32 path]
struct U4x2 { uint4 a, b; };

__device__ __forceinline__ U4x2 ld_opnd(const float* f32p, int row, int col_e) {
    U4x2 r;
    if (f32p) {
        const uint4* p = (const uint4*)&f32p[(size_t)row * EMBED_DIM + col_e];
        r.a = p[0]; r.b = p[1];                       // 8 fp32
    } else {
        size_t o = (size_t)row * EMBED_DIM + col_e;   // 8 bf16 each
        r.a = *(const uint4*)&g_Ahi[o];
        r.b = *(const uint4*)&g_Alo[o];
    }
    return r;
}
__device__ __forceinline__ void st_opnd(__nv_bfloat16* shi, __nv_bfloat16* slo,
                                        uint32_t so, const U4x2& v, bool is_f32) {
    if (is_f32) {
        const float* f = (const float*)&v;
        uint4 H, L;
        split2(f[0], f[1], H.x, L.x); split2(f[2], f[3], H.y, L.y);
        split2(f[4], f[5], H.z, L.z); split2(f[6], f[7], H.w, L.w);
        *(uint4*)&shi[so] = H; *(uint4*)&slo[so] = L;
    } else {
        *(uint4*)&shi[so] = v.a; *(uint4*)&slo[so] = v.b;
    }
}

// =================================================================================
// Tensor-core GEMM, bf16x3 split IN-STAGING (no separate split kernels).
// Batch mode (out_sel_p == -1): blockIdx.z selects (A,W,epilogue) in {Q,K,V}.
// Single mode: A0 fp32 or null (null -> read g_Ahi/g_Alo), W0 fp32.
// =================================================================================
#define GBM 128
#define GBN 128
#define GKC 32
#define GST 40

__global__ void __launch_bounds__(256) gemm_mma_kernel(
    const float* __restrict__ A0, const float* __restrict__ A1, const float* __restrict__ A2,
    const float* __restrict__ W0, const float* __restrict__ W1, const float* __restrict__ W2,
    const float* __restrict__ bias, int out_sel_p, float* ext_out)
{
    int out_sel;
    const float *Af, *Wf;
    if (out_sel_p < 0) {                      // batched QKV: z = 0/1/2
        out_sel = blockIdx.z;
        Af = (blockIdx.z == 0) ? A0 : (blockIdx.z == 1) ? A1 : A2;
        Wf = (blockIdx.z == 0) ? W0 : (blockIdx.z == 1) ? W1 : W2;
    } else {
        out_sel = out_sel_p;
        Af = A0;                              // may be null -> bf16 path
        Wf = W0;
    }
    const bool a_f32 = (Af != nullptr);

    __shared__ __align__(16) __nv_bfloat16 sAhi[GBM * GST];
    __shared__ __align__(16) __nv_bfloat16 sAlo[GBM * GST];
    __shared__ __align__(16) __nv_bfloat16 sBhi[GBN * GST];
    __shared__ __align__(16) __nv_bfloat16 sBlo[GBN * GST];

    const int tid  = threadIdx.x;
    const int lane = tid & 31;
    const int wid  = tid >> 5;
    const int wm0  = (wid & 3) * 32;
    const int wn0  = (wid >> 2) * 64;
    const int m0   = blockIdx.y * GBM;
    const int n0   = blockIdx.x * GBN;

    const int a_r  = lane & 15;
    const int a_c8 = (lane >> 4) << 3;
    const int b_r  = (lane & 7) + (((lane >> 4) & 1) << 3);
    const int b_c8 = ((lane >> 3) & 1) << 3;

    float acc[2][8][4];
    #pragma unroll
    for (int mi = 0; mi < 2; mi++)
        #pragma unroll
        for (int ni = 0; ni < 8; ni++)
            #pragma unroll
            for (int r = 0; r < 4; r++) acc[mi][ni][r] = 0.f;

    int sr[2], sck[2];
    #pragma unroll
    for (int i = 0; i < 2; i++) {
        int f = tid + (i << 8);
        sr[i]  = f >> 2;
        sck[i] = (f & 3) * 8;
    }

    U4x2 rA[2], rB[2];
    #pragma unroll
    for (int i = 0; i < 2; i++) {
        rA[i] = ld_opnd(Af, m0 + sr[i], sck[i]);
        rB[i] = ld_opnd(Wf, n0 + sr[i], sck[i]);
    }

    for (int kb = 0; kb < EMBED_DIM; kb += GKC) {
        __syncthreads();
        #pragma unroll
        for (int i = 0; i < 2; i++) {
            uint32_t so = (uint32_t)(sr[i] * GST + sck[i]);
            st_opnd(sAhi, sAlo, so, rA[i], a_f32);
            st_opnd(sBhi, sBlo, so, rB[i], true);
        }
        __syncthreads();

        if (kb + GKC < EMBED_DIM) {
            #pragma unroll
            for (int i = 0; i < 2; i++) {
                rA[i] = ld_opnd(Af, m0 + sr[i], kb + GKC + sck[i]);
                rB[i] = ld_opnd(Wf, n0 + sr[i], kb + GKC + sck[i]);
            }
        }

        #pragma unroll
        for (int kk = 0; kk < GKC; kk += 16) {
            uint32_t ah[2][4], al[2][4], bb[8][2];
            #pragma unroll
            for (int mi = 0; mi < 2; mi++) {
                uint32_t ad = smem_u32(&sAhi[(wm0 + mi * 16 + a_r) * GST + kk + a_c8]);
                ldm_x4(ah[mi][0], ah[mi][1], ah[mi][2], ah[mi][3], ad);
                ad = smem_u32(&sAlo[(wm0 + mi * 16 + a_r) * GST + kk + a_c8]);
                ldm_x4(al[mi][0], al[mi][1], al[mi][2], al[mi][3], ad);
            }
            #pragma unroll
            for (int np = 0; np < 4; np++) {
                uint32_t ad = smem_u32(&sBhi[(wn0 + np * 16 + b_r) * GST + kk + b_c8]);
                ldm_x4(bb[2 * np][0], bb[2 * np][1], bb[2 * np + 1][0], bb[2 * np + 1][1], ad);
            }
            #pragma unroll
            for (int mi = 0; mi < 2; mi++)
                #pragma unroll
                for (int ni = 0; ni < 8; ni++) mma16816(acc[mi][ni], ah[mi], bb[ni]);
            #pragma unroll
            for (int mi = 0; mi < 2; mi++)
                #pragma unroll
                for (int ni = 0; ni < 8; ni++) mma16816(acc[mi][ni], al[mi], bb[ni]);
            #pragma unroll
            for (int np = 0; np < 4; np++) {
                uint32_t ad = smem_u32(&sBlo[(wn0 + np * 16 + b_r) * GST + kk + b_c8]);
                ldm_x4(bb[2 * np][0], bb[2 * np][1], bb[2 * np + 1][0], bb[2 * np + 1][1], ad);
            }
            #pragma unroll
            for (int mi = 0; mi < 2; mi++)
                #pragma unroll
                for (int ni = 0; ni < 8; ni++) mma16816(acc[mi][ni], ah[mi], bb[ni]);
        }
    }

    const int er = lane >> 2;
    const int ec = (lane & 3) * 2;
    #pragma unroll
    for (int mi = 0; mi < 2; mi++) {
        #pragma unroll
        for (int ni = 0; ni < 8; ni++) {
            int row = m0 + wm0 + mi * 16 + er;
            int col = n0 + wn0 + ni * 8 + ec;
            float v00 = acc[mi][ni][0], v01 = acc[mi][ni][1];
            float v10 = acc[mi][ni][2], v11 = acc[mi][ni][3];
            if (out_sel == OUT_EXT) {
                float b0 = bias ? bias[col] : 0.f, b1 = bias ? bias[col + 1] : 0.f;
                *(float2*)&ext_out[(size_t)row * EMBED_DIM + col] = make_float2(v00 + b0, v01 + b1);
                *(float2*)&ext_out[(size_t)(row + 8) * EMBED_DIM + col] = make_float2(v10 + b0, v11 + b1);
            } else if (out_sel == OUT_V) {
                int bb_ = row >> 11, tok = row & 2047;
                int hh  = col >> 6,  dd  = col & 63;
                size_t base = ((size_t)(bb_ * 16 + hh) * 64 + dd) * SEQ_LEN + tok;
                uint32_t h0, l0, h1, l1;
                split2(v00, v10, h0, l0);
                split2(v01, v11, h1, l1);
                g_Vthi[base]               = __ushort_as_bfloat16((unsigned short)(h0 & 0xffff));
                g_Vthi[base + 8]           = __ushort_as_bfloat16((unsigned short)(h0 >> 16));
                g_Vtlo[base]               = __ushort_as_bfloat16((unsigned short)(l0 & 0xffff));
                g_Vtlo[base + 8]           = __ushort_as_bfloat16((unsigned short)(l0 >> 16));
                g_Vthi[base + SEQ_LEN]     = __ushort_as_bfloat16((unsigned short)(h1 & 0xffff));
                g_Vthi[base + SEQ_LEN + 8] = __ushort_as_bfloat16((unsigned short)(h1 >> 16));
                g_Vtlo[base + SEQ_LEN]     = __ushort_as_bfloat16((unsigned short)(l1 & 0xffff));
                g_Vtlo[base + SEQ_LEN + 8] = __ushort_as_bfloat16((unsigned short)(l1 >> 16));
            } else {
                __nv_bfloat16* hi = (out_sel == OUT_Q) ? g_Qhi : g_Khi;
                __nv_bfloat16* lo = (out_sel == OUT_Q) ? g_Qlo : g_Klo;
                float sc = (out_sel == OUT_Q) ? 0.125f : 1.f;
                uint32_t h, l;
                split2(v00 * sc, v01 * sc, h, l);
                *(uint32_t*)&hi[(size_t)row * EMBED_DIM + col] = h;
                *(uint32_t*)&lo[(size_t)row * EMBED_DIM + col] = l;
                split2(v10 * sc, v11 * sc, h, l);
                *(uint32_t*)&hi[(size_t)(row + 8) * EMBED_DIM + col] = h;
                *(uint32_t*)&lo[(size_t)(row + 8) * EMBED_DIM + col] = l;
            }
        }
    }
}

// =================================================================================
// Tensor-core flash attention (verified math) + cp.async double-buffer:
// cp.async(t+1 -> other buffer) -> compute(t) -> wait -> ONE syncthreads.
// =================================================================================
#define QT 128
#define KT 32
#define KST 72
#define VST 40
#define NT (SEQ_LEN / KT)

__global__ void __launch_bounds__(256) attn_kernel(const int* __restrict__ mask)
{
    __shared__ __align__(16) __nv_bfloat16 sKhi[2][KT * KST];
    __shared__ __align__(16) __nv_bfloat16 sKlo[2][KT * KST];
    __shared__ __align__(16) __nv_bfloat16 sVhi[2][64 * VST];
    __shared__ __align__(16) __nv_bfloat16 sVlo[2][64 * VST];
    __shared__ float mk[2][KT];

    const int tid  = threadIdx.x;
    const int lane = tid & 31;
    const int wid  = tid >> 5;
    const int wm   = wid * 16;
    const int q0   = blockIdx.x * QT;
    const int b    = blockIdx.y >> 4;
    const int h    = blockIdx.y & 15;

    const int er   = lane >> 2;
    const int ec   = (lane & 3) * 2;
    const int b_r  = (lane & 7) + (((lane >> 4) & 1) << 3);
    const int b_c8 = ((lane >> 3) & 1) << 3;

    // fixed per-thread staging indices / addresses
    const int k_key = tid >> 3, k_c8 = (tid & 7) * 8;
    const int v_d   = tid >> 2, v_kc = (tid & 3) * 8;
    const size_t kbase = (size_t)(b * SEQ_LEN + k_key) * EMBED_DIM + h * HEAD_DIM + k_c8;
    const size_t vbase = ((size_t)(b * 16 + h) * HEAD_DIM + v_d) * SEQ_LEN + v_kc;
    uint32_t aKhi[2], aKlo[2], aVhi[2], aVlo[2];
    #pragma unroll
    for (int bf = 0; bf < 2; bf++) {
        aKhi[bf] = smem_u32(&sKhi[bf][k_key * KST + k_c8]);
        aKlo[bf] = smem_u32(&sKlo[bf][k_key * KST + k_c8]);
        aVhi[bf] = smem_u32(&sVhi[bf][v_d * VST + v_kc]);
        aVlo[bf] = smem_u32(&sVlo[bf][v_d * VST + v_kc]);
    }

    // ---- Q fragments direct from gmem
    uint32_t qh[4][4], ql[4][4];
    {
        size_t r0 = (size_t)(b * SEQ_LEN + q0 + wm + er) * EMBED_DIM + h * HEAD_DIM;
        size_t r1 = r0 + 8 * EMBED_DIM;
        #pragma unroll
        for (int c = 0; c < 4; c++) {
            int cc = c * 16 + ec;
            qh[c][0] = *(const uint32_t*)&g_Qhi[r0 + cc];
            qh[c][1] = *(const uint32_t*)&g_Qhi[r1 + cc];
            qh[c][2] = *(const uint32_t*)&g_Qhi[r0 + cc + 8];
            qh[c][3] = *(const uint32_t*)&g_Qhi[r1 + cc + 8];
            ql[c][0] = *(const uint32_t*)&g_Qlo[r0 + cc];
            ql[c][1] = *(const uint32_t*)&g_Qlo[r1 + cc];
            ql[c][2] = *(const uint32_t*)&g_Qlo[r0 + cc + 8];
            ql[c][3] = *(const uint32_t*)&g_Qlo[r1 + cc + 8];
        }
    }

    float m0r = -1e30f, m1r = -1e30f, l0 = 0.f, l1 = 0.f;
    float o[8][4];
    #pragma unroll
    for (int ni = 0; ni < 8; ni++)
        #pragma unroll
        for (int r = 0; r < 4; r++) o[ni][r] = 0.f;

    // ---- preload tile 0 into buffer 0 via cp.async
    {
        CPA16(aKhi[0], (const void*)&g_Khi[kbase]);
        CPA16(aKlo[0], (const void*)&g_Klo[kbase]);
        CPA16(aVhi[0], (const void*)&g_Vthi[vbase]);
        CPA16(aVlo[0], (const void*)&g_Vtlo[vbase]);
        CPA_COMMIT();
        if (tid < KT)
            mk[0][tid] = (mask[b * SEQ_LEN + tid] == 0) ? -1e20f : 0.f;
        CPA_WAIT0();
    }
    __syncthreads();

    for (int ti = 0; ti < NT; ti++) {
        const int cur = ti & 1;
        const int nb  = cur ^ 1;
        const bool nx = (ti + 1) < NT;

        // ---- issue cp.async for next tile (fills idle buffer during compute)
        int nmv = 1;
        if (nx) {
            size_t kg = kbase + (size_t)(ti + 1) * KT * EMBED_DIM;
            size_t vg = vbase + (size_t)(ti + 1) * KT;
            CPA16(aKhi[nb], (const void*)&g_Khi[kg]);
            CPA16(aKlo[nb], (const void*)&g_Klo[kg]);
            CPA16(aVhi[nb], (const void*)&g_Vthi[vg]);
            CPA16(aVlo[nb], (const void*)&g_Vtlo[vg]);
            CPA_COMMIT();
            if (tid < KT) nmv = mask[b * SEQ_LEN + (ti + 1) * KT + tid];
        }

        // ---- S = Q K^T (3 products)
        float s[4][4];
        #pragma unroll
        for (int j = 0; j < 4; j++)
            #pragma unroll
            for (int r = 0; r < 4; r++) s[j][r] = 0.f;
        #pragma unroll
        for (int c = 0; c < 4; c++) {
            uint32_t bb[4][2];
            #pragma unroll
            for (int np = 0; np < 2; np++) {
                uint32_t ad = smem_u32(&sKhi[cur][(np * 16 + b_r) * KST + c * 16 + b_c8]);
                ldm_x4(bb[2*np][0], bb[2*np][1], bb[2*np+1][0], bb[2*np+1][1], ad);
            }
            #pragma unroll
            for (int j = 0; j < 4; j++) mma16816(s[j], qh[c], bb[j]);
            #pragma unroll
            for (int j = 0; j < 4; j++) mma16816(s[j], ql[c], bb[j]);
            #pragma unroll
            for (int np = 0; np < 2; np++) {
                uint32_t ad = smem_u32(&sKlo[cur][(np * 16 + b_r) * KST + c * 16 + b_c8]);
                ldm_x4(bb[2*np][0], bb[2*np][1], bb[2*np+1][0], bb[2*np+1][1], ad);
            }
            #pragma unroll
            for (int j = 0; j < 4; j++) mma16816(s[j], qh[c], bb[j]);
        }

        // ---- mask + register FA2 softmax
        #pragma unroll
        for (int j = 0; j < 4; j++) {
            float a0 = mk[cur][j * 8 + ec], a1 = mk[cur][j * 8 + ec + 1];
            s[j][0] += a0; s[j][1] += a1; s[j][2] += a0; s[j][3] += a1;
        }
        float r0 = fmaxf(fmaxf(s[0][0], s[0][1]), fmaxf(s[1][0], s[1][1]));
        r0 = fmaxf(r0, fmaxf(fmaxf(s[2][0], s[2][1]), fmaxf(s[3][0], s[3][1])));
        float r1 = fmaxf(fmaxf(s[0][2], s[0][3]), fmaxf(s[1][2], s[1][3]));
        r1 = fmaxf(r1, fmaxf(fmaxf(s[2][2], s[2][3]), fmaxf(s[3][2], s[3][3])));
        r0 = fmaxf(r0, __shfl_xor_sync(0xffffffffu, r0, 1));
        r0 = fmaxf(r0, __shfl_xor_sync(0xffffffffu, r0, 2));
        r1 = fmaxf(r1, __shfl_xor_sync(0xffffffffu, r1, 1));
        r1 = fmaxf(r1, __shfl_xor_sync(0xffffffffu, r1, 2));
        float mn0 = fmaxf(m0r, r0), mn1 = fmaxf(m1r, r1);
        float al0 = __expf(m0r - mn0), al1 = __expf(m1r - mn1);
        m0r = mn0; m1r = mn1;

        float p[4][4], sum0 = 0.f, sum1 = 0.f;
        #pragma unroll
        for (int j = 0; j < 4; j++) {
            p[j][0] = __expf(s[j][0] - mn0); p[j][1] = __expf(s[j][1] - mn0);
            p[j][2] = __expf(s[j][2] - mn1); p[j][3] = __expf(s[j][3] - mn1);
            sum0 += p[j][0] + p[j][1];
            sum1 += p[j][2] + p[j][3];
        }
        sum0 += __shfl_xor_sync(0xffffffffu, sum0, 1);
        sum0 += __shfl_xor_sync(0xffffffffu, sum0, 2);
        sum1 += __shfl_xor_sync(0xffffffffu, sum1, 1);
        sum1 += __shfl_xor_sync(0xffffffffu, sum1, 2);
        l0 = l0 * al0 + sum0;
        l1 = l1 * al1 + sum1;
        #pragma unroll
        for (int ni = 0; ni < 8; ni++) {
            o[ni][0] *= al0; o[ni][1] *= al0; o[ni][2] *= al1; o[ni][3] *= al1;
        }

        // ---- P -> A-frags, split hi/lo
        uint32_t ph[2][4], pl[2][4];
        #pragma unroll
        for (int c = 0; c < 2; c++) {
            int j0 = 2 * c, j1 = 2 * c + 1;
            split2(p[j0][0], p[j0][1], ph[c][0], pl[c][0]);
            split2(p[j0][2], p[j0][3], ph[c][1], pl[c][1]);
            split2(p[j1][0], p[j1][1], ph[c][2], pl[c][2]);
            split2(p[j1][2], p[j1][3], ph[c][3], pl[c][3]);
        }

        // ---- O += P V (3 products)
        #pragma unroll
        for (int c = 0; c < 2; c++) {
            uint32_t vb[8][2];
            #pragma unroll
            for (int np = 0; np < 4; np++) {
                uint32_t ad = smem_u32(&sVhi[cur][(np * 16 + b_r) * VST + c * 16 + b_c8]);
                ldm_x4(vb[2*np][0], vb[2*np][1], vb[2*np+1][0], vb[2*np+1][1], ad);
            }
            #pragma unroll
            for (int ni = 0; ni < 8; ni++) mma16816(o[ni], ph[c], vb[ni]);
            #pragma unroll
            for (int ni = 0; ni < 8; ni++) mma16816(o[ni], pl[c], vb[ni]);
            #pragma unroll
            for (int np = 0; np < 4; np++) {
                uint32_t ad = smem_u32(&sVlo[cur][(np * 16 + b_r) * VST + c * 16 + b_c8]);
                ldm_x4(vb[2*np][0], vb[2*np][1], vb[2*np+1][0], vb[2*np+1][1], ad);
            }
            #pragma unroll
            for (int ni = 0; ni < 8; ni++) mma16816(o[ni], ph[c], vb[ni]);
        }

        // ---- complete next-tile fill; one sync per iteration
        if (nx) {
            CPA_WAIT0();
            if (tid < KT) mk[nb][tid] = (nmv == 0) ? -1e20f : 0.f;
        }
        __syncthreads();
    }

    // ---- epilogue: normalize, split, write AO hi/lo into GEMM-A buffers
    {
        float i0 = 1.f / l0, i1 = 1.f / l1;
        size_t r0o = (size_t)(b * SEQ_LEN + q0 + wm + er) * EMBED_DIM + h * HEAD_DIM;
        size_t r1o = r0o + 8 * EMBED_DIM;
        #pragma unroll
        for (int ni = 0; ni < 8; ni++) {
            int d = ni * 8 + ec;
            uint32_t hh, ll;
            split2(o[ni][0] * i0, o[ni][1] * i0, hh, ll);
            *(uint32_t*)&g_Ahi[r0o + d] = hh;
            *(uint32_t*)&g_Alo[r0o + d] = ll;
            split2(o[ni][2] * i1, o[ni][3] * i1, hh, ll);
            *(uint32_t*)&g_Ahi[r1o + d] = hh;
            *(uint32_t*)&g_Alo[r1o + d] = ll;
        }
    }
}

// =================================================================================
// kernel_launch: THREE launches, no runtime API calls.
// =================================================================================
extern "C" void kernel_launch(void* const* d_in, const int* in_sizes, int n_in,
                              void* d_out, int out_size)
{
    const float* values = (const float*)d_in[0];
    const float* keys   = (const float*)d_in[1];
    const float* query  = (const float*)d_in[2];
    const int*   mask   = (const int*)  d_in[3];
    const float* W_q    = (const float*)d_in[4];
    const float* W_k    = (const float*)d_in[5];
    const float* W_v    = (const float*)d_in[6];
    const float* W_o    = (const float*)d_in[7];
    const float* b_o    = (const float*)d_in[8];
    float* out = (float*)d_out;

    // batched QKV projections: z=0 -> Q, z=1 -> K, z=2 -> V
    dim3 qkv_grid(EMBED_DIM / GBN, NTOK / GBM, 3);      // (8, 32, 3) = 768 CTAs
    gemm_mma_kernel<<<qkv_grid, 256>>>(query, keys, values,
                                       W_q, W_k, W_v,
                                       nullptr, -1, nullptr);

    dim3 agrid(SEQ_LEN / QT, 2 * 16);                   // 512 CTAs
    attn_kernel<<<agrid, 256>>>(mask);

    dim3 ogrid(EMBED_DIM / GBN, NTOK / GBM);            // 256 CTAs
    gemm_mma_kernel<<<ogrid, 256>>>(nullptr, nullptr, nullptr,
                                    W_o, nullptr, nullptr,
                                    b_o, OUT_EXT, out);
}